// round 1
// baseline (speedup 1.0000x reference)
#include <cuda_runtime.h>
#include <math.h>

// Problem constants
#define BATCH 2
#define KLEN  512
#define LSEQ  1024          // 2*K
#define EMB   1024
#define NHEAD 16
#define DHEAD 64
#define NLAYER 12
#define FFDIM 4096
#define DIN   64
#define LN_EPS 1e-5f

// Scratch (device globals; allocation is forbidden)
__device__ float g_x   [BATCH * LSEQ * EMB];        // residual stream
__device__ float g_h   [BATCH * LSEQ * EMB];        // layernorm output
__device__ float g_qkv [BATCH * LSEQ * 3 * EMB];    // qkv
__device__ float g_att [BATCH * LSEQ * EMB];        // attention output (head-major merged)
__device__ float g_ff  [BATCH * LSEQ * FFDIM];      // mlp hidden

// ---------------------------------------------------------------------------
// Kernel 1: combine (xs, ys) -> zs and project with w_in  =>  g_x [B*L, E]
// grid: (E/256, B*L), block: 256
// ---------------------------------------------------------------------------
__global__ void embed_kernel(const float* __restrict__ xs,
                             const float* __restrict__ ys,
                             const float* __restrict__ w_in,
                             const float* __restrict__ b_in)
{
    __shared__ float z[DIN];
    const int row = blockIdx.y;             // 0 .. B*L-1
    const int b   = row / LSEQ;
    const int l   = row % LSEQ;
    const int k   = l >> 1;
    const int tid = threadIdx.x;

    if (tid < DIN) {
        float v;
        if ((l & 1) == 0) {
            v = xs[(b * KLEN + k) * DIN + tid];
        } else {
            v = (tid == 0) ? ys[b * KLEN + k] : 0.0f;
        }
        z[tid] = v;
    }
    __syncthreads();

    const int n = blockIdx.x * blockDim.x + tid;
    float acc = b_in[n];
#pragma unroll 16
    for (int d = 0; d < DIN; ++d)
        acc += z[d] * w_in[d * EMB + n];
    g_x[row * EMB + n] = acc;
}

// ---------------------------------------------------------------------------
// Kernel 2: LayerNorm. grid: B*L, block: 256
// ---------------------------------------------------------------------------
__global__ void ln_kernel(const float* __restrict__ x,
                          const float* __restrict__ s,
                          const float* __restrict__ bb,
                          float* __restrict__ out)
{
    __shared__ float r1[256];
    __shared__ float r2[256];
    __shared__ float stats[2];
    const int row = blockIdx.x;
    const int tid = threadIdx.x;
    const float* xr = x + (size_t)row * EMB;

    float sum = 0.f, sq = 0.f;
#pragma unroll
    for (int c = tid; c < EMB; c += 256) {
        float v = xr[c];
        sum += v; sq += v * v;
    }
    r1[tid] = sum; r2[tid] = sq;
    __syncthreads();
    for (int off = 128; off > 0; off >>= 1) {
        if (tid < off) { r1[tid] += r1[tid + off]; r2[tid] += r2[tid + off]; }
        __syncthreads();
    }
    if (tid == 0) {
        float m = r1[0] * (1.0f / EMB);
        float v = r2[0] * (1.0f / EMB) - m * m;
        stats[0] = m;
        stats[1] = rsqrtf(v + LN_EPS);
    }
    __syncthreads();
    const float m = stats[0], rstd = stats[1];
    float* outr = out + (size_t)row * EMB;
#pragma unroll
    for (int c = tid; c < EMB; c += 256)
        outr[c] = (xr[c] - m) * rstd * s[c] + bb[c];
}

// ---------------------------------------------------------------------------
// Kernel 3: SGEMM 128x128x8, 256 threads, 8x8 per thread.
// C[M,N] = A[M,K] @ B[K,N] + bias  (+ R residual) (optional exact GELU)
// Requires M%128==0, N%128==0, K%8==0 (all shapes here satisfy this).
// ---------------------------------------------------------------------------
template <bool RES, bool GELU>
__global__ __launch_bounds__(256, 2)
void sgemm128(const float* __restrict__ A, const float* __restrict__ B,
              const float* __restrict__ bias, const float* __restrict__ R,
              float* __restrict__ C, int M, int N, int K)
{
    __shared__ __align__(16) float As[8][128];
    __shared__ __align__(16) float Bs[8][128];

    const int tid = threadIdx.x;
    const int bx = blockIdx.x, by = blockIdx.y;
    const int tx = tid & 15;        // 0..15
    const int ty = tid >> 4;        // 0..15

    const int aRow = tid >> 1;          // 0..127
    const int aCol = (tid & 1) * 4;     // 0 or 4
    const int bRow = tid >> 5;          // 0..7
    const int bCol = (tid & 31) * 4;    // 0..124

    const float* Aptr = A + (size_t)(by * 128 + aRow) * K + aCol;
    const float* Bptr = B + (size_t)bRow * N + bx * 128 + bCol;

    float acc[8][8];
#pragma unroll
    for (int i = 0; i < 8; ++i)
#pragma unroll
        for (int j = 0; j < 8; ++j) acc[i][j] = 0.f;

    for (int kt = 0; kt < K; kt += 8) {
        float4 av = *(const float4*)(Aptr + kt);
        As[aCol + 0][aRow] = av.x;
        As[aCol + 1][aRow] = av.y;
        As[aCol + 2][aRow] = av.z;
        As[aCol + 3][aRow] = av.w;
        float4 bv = *(const float4*)(Bptr + (size_t)kt * N);
        *(float4*)&Bs[bRow][bCol] = bv;
        __syncthreads();

#pragma unroll
        for (int k = 0; k < 8; ++k) {
            float ar[8], br[8];
            float4 a0 = *(const float4*)&As[k][ty * 8];
            float4 a1 = *(const float4*)&As[k][ty * 8 + 4];
            float4 b0 = *(const float4*)&Bs[k][tx * 8];
            float4 b1 = *(const float4*)&Bs[k][tx * 8 + 4];
            ar[0]=a0.x; ar[1]=a0.y; ar[2]=a0.z; ar[3]=a0.w;
            ar[4]=a1.x; ar[5]=a1.y; ar[6]=a1.z; ar[7]=a1.w;
            br[0]=b0.x; br[1]=b0.y; br[2]=b0.z; br[3]=b0.w;
            br[4]=b1.x; br[5]=b1.y; br[6]=b1.z; br[7]=b1.w;
#pragma unroll
            for (int i = 0; i < 8; ++i)
#pragma unroll
                for (int j = 0; j < 8; ++j)
                    acc[i][j] = fmaf(ar[i], br[j], acc[i][j]);
        }
        __syncthreads();
    }

    const int row0 = by * 128 + ty * 8;
    const int col0 = bx * 128 + tx * 8;
#pragma unroll
    for (int i = 0; i < 8; ++i) {
        const size_t rbase = (size_t)(row0 + i) * N + col0;
#pragma unroll
        for (int j = 0; j < 8; ++j) {
            float v = acc[i][j] + bias[col0 + j];
            if (RES)  v += R[rbase + j];
            if (GELU) v = 0.5f * v * (1.0f + erff(v * 0.70710678118654752f));
            C[rbase + j] = v;
        }
    }
}

// ---------------------------------------------------------------------------
// Kernel 4: causal attention, one block per (query l, head h, batch b).
// qkv layout: [B*L, 3*E], column = part*E + h*64 + d.
// Output g_att: [B*L, E] with column h*64 + d.
// ---------------------------------------------------------------------------
__global__ void attn_kernel(const float* __restrict__ qkv,
                            float* __restrict__ out)
{
    __shared__ float q[DHEAD];
    __shared__ float sc[LSEQ];
    __shared__ float red[256];
    __shared__ float stats[2];

    const int l = blockIdx.x;
    const int h = blockIdx.y;
    const int b = blockIdx.z;
    const int tid = threadIdx.x;
    const int cnt = l + 1;                       // causal: keys 0..l

    const size_t rowstride = 3 * EMB;
    const size_t qbase = ((size_t)(b * LSEQ + l)) * rowstride + h * DHEAD;

    if (tid < DHEAD) q[tid] = qkv[qbase + tid];
    __syncthreads();

    // --- scores ---
    float lmax = -1e30f;
    for (int m = tid; m < cnt; m += 256) {
        const float* kr = qkv + ((size_t)(b * LSEQ + m)) * rowstride + EMB + h * DHEAD;
        float dot = 0.f;
#pragma unroll 16
        for (int d = 0; d < DHEAD; ++d)
            dot = fmaf(q[d], kr[d], dot);
        dot *= 0.125f;                            // 1/sqrt(64)
        sc[m] = dot;
        lmax = fmaxf(lmax, dot);
    }
    red[tid] = lmax;
    __syncthreads();
    for (int off = 128; off > 0; off >>= 1) {
        if (tid < off) red[tid] = fmaxf(red[tid], red[tid + off]);
        __syncthreads();
    }
    if (tid == 0) stats[0] = red[0];
    __syncthreads();
    const float mx = stats[0];

    float lsum = 0.f;
    for (int m = tid; m < cnt; m += 256) {
        float e = __expf(sc[m] - mx);
        sc[m] = e;
        lsum += e;
    }
    __syncthreads();    // sc writes done before reuse of red
    red[tid] = lsum;
    __syncthreads();
    for (int off = 128; off > 0; off >>= 1) {
        if (tid < off) red[tid] += red[tid + off];
        __syncthreads();
    }
    if (tid == 0) stats[1] = 1.0f / red[0];
    __syncthreads();
    const float inv = stats[1];

    // --- output: o[d] = sum_m sc[m] * V[m][d] ---
    const int d   = tid & (DHEAD - 1);
    const int seg = tid >> 6;                    // 0..3
    float acc = 0.f;
    for (int m = seg; m < cnt; m += 4) {
        const float* vr = qkv + ((size_t)(b * LSEQ + m)) * rowstride + 2 * EMB + h * DHEAD;
        acc = fmaf(sc[m], vr[d], acc);
    }
    red[tid] = acc;
    __syncthreads();
    if (seg == 0) {
        float o = (red[d] + red[64 + d] + red[128 + d] + red[192 + d]) * inv;
        out[((size_t)(b * LSEQ + l)) * EMB + h * DHEAD + d] = o;
    }
}

// ---------------------------------------------------------------------------
// Kernel 5: final head. out[b,k] = x[b, 2k, :] . w_out + b_out
// grid: B*K, block: 256
// ---------------------------------------------------------------------------
__global__ void head_kernel(const float* __restrict__ x,
                            const float* __restrict__ w_out,
                            const float* __restrict__ b_out,
                            float* __restrict__ out)
{
    __shared__ float red[256];
    const int idx = blockIdx.x;                  // 0..B*K-1
    const int b = idx / KLEN;
    const int k = idx % KLEN;
    const int tid = threadIdx.x;
    const float* xr = x + ((size_t)(b * LSEQ + 2 * k)) * EMB;
    float acc = 0.f;
#pragma unroll
    for (int c = tid; c < EMB; c += 256)
        acc = fmaf(xr[c], w_out[c], acc);
    red[tid] = acc;
    __syncthreads();
    for (int off = 128; off > 0; off >>= 1) {
        if (tid < off) red[tid] += red[tid + off];
        __syncthreads();
    }
    if (tid == 0) out[idx] = red[0] + b_out[0];
}

// ---------------------------------------------------------------------------
// Launch
// ---------------------------------------------------------------------------
extern "C" void kernel_launch(void* const* d_in, const int* in_sizes, int n_in,
                              void* d_out, int out_size)
{
    const float* xs     = (const float*)d_in[0];
    const float* ys     = (const float*)d_in[1];
    const float* w_in   = (const float*)d_in[2];
    const float* b_in   = (const float*)d_in[3];
    const float* qkv_w  = (const float*)d_in[4];
    const float* qkv_b  = (const float*)d_in[5];
    const float* proj_w = (const float*)d_in[6];
    const float* proj_b = (const float*)d_in[7];
    const float* ln1_s  = (const float*)d_in[8];
    const float* ln1_b  = (const float*)d_in[9];
    const float* ln2_s  = (const float*)d_in[10];
    const float* ln2_b  = (const float*)d_in[11];
    const float* mlp_w1 = (const float*)d_in[12];
    const float* mlp_b1 = (const float*)d_in[13];
    const float* mlp_w2 = (const float*)d_in[14];
    const float* mlp_b2 = (const float*)d_in[15];
    const float* w_out  = (const float*)d_in[16];
    const float* b_out  = (const float*)d_in[17];
    float* out = (float*)d_out;

    float *x, *h, *qkv, *att, *ff;
    cudaGetSymbolAddress((void**)&x,   g_x);
    cudaGetSymbolAddress((void**)&h,   g_h);
    cudaGetSymbolAddress((void**)&qkv, g_qkv);
    cudaGetSymbolAddress((void**)&att, g_att);
    cudaGetSymbolAddress((void**)&ff,  g_ff);

    const int M = BATCH * LSEQ;   // 2048

    embed_kernel<<<dim3(EMB / 256, M), 256>>>(xs, ys, w_in, b_in);

    for (int lay = 0; lay < NLAYER; ++lay) {
        const float* qw  = qkv_w  + (size_t)lay * EMB * 3 * EMB;
        const float* qb  = qkv_b  + (size_t)lay * 3 * EMB;
        const float* pw  = proj_w + (size_t)lay * EMB * EMB;
        const float* pb  = proj_b + (size_t)lay * EMB;
        const float* s1  = ln1_s  + (size_t)lay * EMB;
        const float* c1  = ln1_b  + (size_t)lay * EMB;
        const float* s2  = ln2_s  + (size_t)lay * EMB;
        const float* c2  = ln2_b  + (size_t)lay * EMB;
        const float* w1  = mlp_w1 + (size_t)lay * EMB * FFDIM;
        const float* bb1 = mlp_b1 + (size_t)lay * FFDIM;
        const float* w2  = mlp_w2 + (size_t)lay * FFDIM * EMB;
        const float* bb2 = mlp_b2 + (size_t)lay * EMB;

        // ln1
        ln_kernel<<<M, 256>>>(x, s1, c1, h);
        // qkv = h @ qw + qb
        sgemm128<false, false><<<dim3(3 * EMB / 128, M / 128), 256>>>(
            h, qw, qb, nullptr, qkv, M, 3 * EMB, EMB);
        // attention
        attn_kernel<<<dim3(LSEQ, NHEAD, BATCH), 256>>>(qkv, att);
        // x = x + att @ pw + pb
        sgemm128<true, false><<<dim3(EMB / 128, M / 128), 256>>>(
            att, pw, pb, x, x, M, EMB, EMB);
        // ln2
        ln_kernel<<<M, 256>>>(x, s2, c2, h);
        // ff = gelu(h @ w1 + b1)
        sgemm128<false, true><<<dim3(FFDIM / 128, M / 128), 256>>>(
            h, w1, bb1, nullptr, ff, M, FFDIM, EMB);
        // x = x + ff @ w2 + b2
        sgemm128<true, false><<<dim3(EMB / 128, M / 128), 256>>>(
            ff, w2, bb2, x, x, M, EMB, FFDIM);
    }

    head_kernel<<<BATCH * KLEN, 256>>>(x, w_out, b_out, out);
}

// round 3
// speedup vs baseline: 3.1353x; 3.1353x over previous
#include <cuda_runtime.h>
#include <cuda_bf16.h>
#include <math.h>
#include <stdint.h>

#define BATCH 2
#define KLEN  512
#define LSEQ  1024
#define EMB   1024
#define NHEAD 16
#define DHEAD 64
#define NLAYER 12
#define FFDIM 4096
#define DIN   64
#define LN_EPS 1e-5f
#define MROWS (BATCH * LSEQ)   // 2048

// ---------------------------------------------------------------------------
// Scratch (device globals; allocation is forbidden)
// ---------------------------------------------------------------------------
__device__ float g_x   [MROWS * EMB];
__device__ float g_qkv [MROWS * 3 * EMB];
__device__ __nv_bfloat16 g_hh[MROWS * EMB];
__device__ __nv_bfloat16 g_hl[MROWS * EMB];
__device__ __nv_bfloat16 g_ah[MROWS * EMB];
__device__ __nv_bfloat16 g_al[MROWS * EMB];
__device__ __nv_bfloat16 g_fh[MROWS * FFDIM];
__device__ __nv_bfloat16 g_fl[MROWS * FFDIM];
// transposed + split weights: [layer][N][K]
__device__ __nv_bfloat16 g_wqh[NLAYER * 3 * EMB * EMB];
__device__ __nv_bfloat16 g_wql[NLAYER * 3 * EMB * EMB];
__device__ __nv_bfloat16 g_wph[NLAYER * EMB * EMB];
__device__ __nv_bfloat16 g_wpl[NLAYER * EMB * EMB];
__device__ __nv_bfloat16 g_w1h[NLAYER * FFDIM * EMB];
__device__ __nv_bfloat16 g_w1l[NLAYER * FFDIM * EMB];
__device__ __nv_bfloat16 g_w2h[NLAYER * EMB * FFDIM];
__device__ __nv_bfloat16 g_w2l[NLAYER * EMB * FFDIM];

// ---------------------------------------------------------------------------
// Helpers
// ---------------------------------------------------------------------------
__device__ __forceinline__ uint32_t smem_u32(const void* p) {
    uint32_t a;
    asm("{ .reg .u64 t; cvta.to.shared.u64 t, %1; cvt.u32.u64 %0, t; }" : "=r"(a) : "l"(p));
    return a;
}
__device__ __forceinline__ void cp_async16(uint32_t s, const void* g) {
    asm volatile("cp.async.cg.shared.global [%0], [%1], 16;" :: "r"(s), "l"(g));
}
#define CP_COMMIT() asm volatile("cp.async.commit_group;" ::: "memory")
#define CP_WAIT(n)  asm volatile("cp.async.wait_group %0;" :: "n"(n) : "memory")

__device__ __forceinline__ uint32_t lds32(uint32_t a) {
    uint32_t v;
    asm volatile("ld.shared.b32 %0, [%1];" : "=r"(v) : "r"(a));
    return v;
}
__device__ __forceinline__ void mma16816(float* d,
    uint32_t a0, uint32_t a1, uint32_t a2, uint32_t a3, uint32_t b0, uint32_t b1) {
    asm volatile(
        "mma.sync.aligned.m16n8k16.row.col.f32.bf16.bf16.f32 "
        "{%0,%1,%2,%3}, {%4,%5,%6,%7}, {%8,%9}, {%0,%1,%2,%3};"
        : "+f"(d[0]), "+f"(d[1]), "+f"(d[2]), "+f"(d[3])
        : "r"(a0), "r"(a1), "r"(a2), "r"(a3), "r"(b0), "r"(b1));
}
__device__ __forceinline__ void split_bf16(float v, __nv_bfloat16& hi, __nv_bfloat16& lo) {
    hi = __float2bfloat16(v);
    lo = __float2bfloat16(v - __bfloat162float(hi));
}

// ---------------------------------------------------------------------------
// Embed
// ---------------------------------------------------------------------------
__global__ void embed_kernel(const float* __restrict__ xs, const float* __restrict__ ys,
                             const float* __restrict__ w_in, const float* __restrict__ b_in)
{
    __shared__ float z[DIN];
    const int row = blockIdx.y, b = row / LSEQ, l = row % LSEQ, k = l >> 1;
    const int tid = threadIdx.x;
    if (tid < DIN) {
        float v;
        if ((l & 1) == 0) v = xs[(b * KLEN + k) * DIN + tid];
        else              v = (tid == 0) ? ys[b * KLEN + k] : 0.0f;
        z[tid] = v;
    }
    __syncthreads();
    const int n = blockIdx.x * blockDim.x + tid;
    float acc = b_in[n];
#pragma unroll 16
    for (int d = 0; d < DIN; ++d) acc += z[d] * w_in[d * EMB + n];
    g_x[row * EMB + n] = acc;
}

// ---------------------------------------------------------------------------
// LayerNorm -> bf16 hi/lo
// ---------------------------------------------------------------------------
__global__ void ln_kernel(const float* __restrict__ x,
                          const float* __restrict__ s, const float* __restrict__ bb,
                          __nv_bfloat16* __restrict__ ohi, __nv_bfloat16* __restrict__ olo)
{
    __shared__ float r1[256], r2[256], stats[2];
    const int row = blockIdx.x, tid = threadIdx.x;
    const float* xr = x + (size_t)row * EMB;
    float sum = 0.f, sq = 0.f;
#pragma unroll
    for (int c = tid; c < EMB; c += 256) { float v = xr[c]; sum += v; sq += v * v; }
    r1[tid] = sum; r2[tid] = sq;
    __syncthreads();
    for (int off = 128; off > 0; off >>= 1) {
        if (tid < off) { r1[tid] += r1[tid + off]; r2[tid] += r2[tid + off]; }
        __syncthreads();
    }
    if (tid == 0) {
        float m = r1[0] * (1.0f / EMB);
        float v = r2[0] * (1.0f / EMB) - m * m;
        stats[0] = m; stats[1] = rsqrtf(v + LN_EPS);
    }
    __syncthreads();
    const float m = stats[0], rstd = stats[1];
#pragma unroll
    for (int c = tid; c < EMB; c += 256) {
        float v = (xr[c] - m) * rstd * s[c] + bb[c];
        __nv_bfloat16 hi, lo; split_bf16(v, hi, lo);
        ohi[(size_t)row * EMB + c] = hi;
        olo[(size_t)row * EMB + c] = lo;
    }
}

// ---------------------------------------------------------------------------
// Weight transpose + split: W[layer][K][N] -> T[layer][N][K] (hi, lo)
// ---------------------------------------------------------------------------
__global__ void transpose_split(const float* __restrict__ W,
                                __nv_bfloat16* __restrict__ Th, __nv_bfloat16* __restrict__ Tl,
                                int K, int N)
{
    __shared__ float t[32][33];
    const int lay = blockIdx.z;
    const float* Ws = W + (size_t)lay * K * N;
    __nv_bfloat16* Ths = Th + (size_t)lay * K * N;
    __nv_bfloat16* Tls = Tl + (size_t)lay * K * N;
    const int n0 = blockIdx.x * 32, k0 = blockIdx.y * 32;
    for (int i = threadIdx.y; i < 32; i += 8)
        t[i][threadIdx.x] = Ws[(size_t)(k0 + i) * N + n0 + threadIdx.x];
    __syncthreads();
    for (int i = threadIdx.y; i < 32; i += 8) {
        float v = t[threadIdx.x][i];
        __nv_bfloat16 hi, lo; split_bf16(v, hi, lo);
        size_t o = (size_t)(n0 + i) * K + k0 + threadIdx.x;
        Ths[o] = hi; Tls[o] = lo;
    }
}

// ---------------------------------------------------------------------------
// Split-bf16 GEMM via mma.sync (m16n8k16), 128x128 tile, cp.async 2-stage.
// C[M,N] = (Ah+Al)[M,K] @ (Bh+Bl)[N,K]^T  (3 split terms), +bias, opt res/gelu.
// smem stage: Ah,Al,Bh,Bl each 128 rows x 80B (32 bf16 + 8 pad). 40KB/stage.
// ---------------------------------------------------------------------------
#define RSTRIDE 80
#define MAT_BYTES (128 * RSTRIDE)          // 10240
#define STAGE_BYTES (4 * MAT_BYTES)        // 40960
#define GEMM_SMEM (2 * STAGE_BYTES)        // 81920

template <bool RES, bool GELU, bool OUT_F32, bool OUT_BF16>
__global__ void __launch_bounds__(256, 1) gemm_mma(
    const __nv_bfloat16* __restrict__ Ah, const __nv_bfloat16* __restrict__ Al,
    const __nv_bfloat16* __restrict__ Bh, const __nv_bfloat16* __restrict__ Bl,
    const float* __restrict__ bias, const float* __restrict__ Rres,
    float* __restrict__ C, __nv_bfloat16* __restrict__ Chi, __nv_bfloat16* __restrict__ Clo,
    int M, int N, int K)
{
    extern __shared__ char smem[];
    const uint32_t sbase = smem_u32(smem);
    const int tid = threadIdx.x, wid = tid >> 5, lane = tid & 31;
    const int m0 = blockIdx.y * 128, n0 = blockIdx.x * 128;
    const int wm = wid & 1, wn = wid >> 1;           // warp tile: 64(m) x 32(n)
    const int g = lane >> 2, q = lane & 3;

    // load mapping: thread -> (row, 32B chunk-pair)
    const int lrow = tid >> 1;
    const int lcc  = (tid & 1) * 2;                  // 16B-chunk index 0 or 2
    const uint32_t soff = (uint32_t)(lrow * RSTRIDE + lcc * 16);

    float acc[4][4][4];
#pragma unroll
    for (int i = 0; i < 4; ++i)
#pragma unroll
        for (int j = 0; j < 4; ++j)
#pragma unroll
            for (int r = 0; r < 4; ++r) acc[i][j][r] = 0.f;

    const int CH = K >> 5;

    auto load_stage = [&](int c, int buf) {
        const int k0 = c << 5;
        const uint32_t sb = sbase + buf * STAGE_BYTES + soff;
        const size_t ga = (size_t)(m0 + lrow) * K + k0 + lcc * 8;
        const size_t gb = (size_t)(n0 + lrow) * K + k0 + lcc * 8;
        cp_async16(sb,                     Ah + ga);
        cp_async16(sb + 16,                Ah + ga + 8);
        cp_async16(sb + MAT_BYTES,         Al + ga);
        cp_async16(sb + MAT_BYTES + 16,    Al + ga + 8);
        cp_async16(sb + 2 * MAT_BYTES,     Bh + gb);
        cp_async16(sb + 2 * MAT_BYTES + 16, Bh + gb + 8);
        cp_async16(sb + 3 * MAT_BYTES,     Bl + gb);
        cp_async16(sb + 3 * MAT_BYTES + 16, Bl + gb + 8);
    };

    load_stage(0, 0);
    CP_COMMIT();

    for (int c = 0; c < CH; ++c) {
        if (c + 1 < CH) { load_stage(c + 1, (c + 1) & 1); CP_COMMIT(); CP_WAIT(1); }
        else            { CP_WAIT(0); }
        __syncthreads();

        const uint32_t sA = sbase + (c & 1) * STAGE_BYTES;
        const uint32_t sB = sA + 2 * MAT_BYTES;
#pragma unroll
        for (int ks = 0; ks < 2; ++ks) {
            const int kb = ks * 16 + q * 2;          // bf16 col within chunk
            // B fragments (hi & lo) for 4 n-tiles
            uint32_t bh[4][2], bl[4][2];
#pragma unroll
            for (int nt = 0; nt < 4; ++nt) {
                const uint32_t ba = sB + (uint32_t)((wn * 32 + nt * 8 + g) * RSTRIDE + kb * 2);
                bh[nt][0] = lds32(ba);       bh[nt][1] = lds32(ba + 16);
                bl[nt][0] = lds32(ba + MAT_BYTES); bl[nt][1] = lds32(ba + MAT_BYTES + 16);
            }
#pragma unroll
            for (int mt = 0; mt < 4; ++mt) {
                const uint32_t aa = sA + (uint32_t)((wm * 64 + mt * 16 + g) * RSTRIDE + kb * 2);
                const uint32_t ah0 = lds32(aa);
                const uint32_t ah1 = lds32(aa + 8 * RSTRIDE);
                const uint32_t ah2 = lds32(aa + 16);
                const uint32_t ah3 = lds32(aa + 8 * RSTRIDE + 16);
                const uint32_t al0 = lds32(aa + MAT_BYTES);
                const uint32_t al1 = lds32(aa + MAT_BYTES + 8 * RSTRIDE);
                const uint32_t al2 = lds32(aa + MAT_BYTES + 16);
                const uint32_t al3 = lds32(aa + MAT_BYTES + 8 * RSTRIDE + 16);
#pragma unroll
                for (int nt = 0; nt < 4; ++nt) {
                    mma16816(acc[mt][nt], ah0, ah1, ah2, ah3, bh[nt][0], bh[nt][1]);
                    mma16816(acc[mt][nt], ah0, ah1, ah2, ah3, bl[nt][0], bl[nt][1]);
                    mma16816(acc[mt][nt], al0, al1, al2, al3, bh[nt][0], bh[nt][1]);
                }
            }
        }
        __syncthreads();
    }

    // epilogue: direct stores (float2 / bf16x2)
#pragma unroll
    for (int nt = 0; nt < 4; ++nt) {
        const int col = n0 + wn * 32 + nt * 8 + q * 2;
        const float bia0 = bias[col], bia1 = bias[col + 1];
#pragma unroll
        for (int mt = 0; mt < 4; ++mt) {
#pragma unroll
            for (int h2 = 0; h2 < 2; ++h2) {
                const int row = m0 + wm * 64 + mt * 16 + g + h2 * 8;
                float v0 = acc[mt][nt][h2 * 2 + 0] + bia0;
                float v1 = acc[mt][nt][h2 * 2 + 1] + bia1;
                const size_t o = (size_t)row * N + col;
                if (RES) { v0 += Rres[o]; v1 += Rres[o + 1]; }
                if (GELU) {
                    v0 = 0.5f * v0 * (1.0f + erff(v0 * 0.70710678118654752f));
                    v1 = 0.5f * v1 * (1.0f + erff(v1 * 0.70710678118654752f));
                }
                if (OUT_F32) { float2 fv = {v0, v1}; *(float2*)(C + o) = fv; }
                if (OUT_BF16) {
                    __nv_bfloat16 h0, l0, h1, l1;
                    split_bf16(v0, h0, l0); split_bf16(v1, h1, l1);
                    __nv_bfloat162 hv; hv.x = h0; hv.y = h1;
                    __nv_bfloat162 lv; lv.x = l0; lv.y = l1;
                    *(__nv_bfloat162*)(Chi + o) = hv;
                    *(__nv_bfloat162*)(Clo + o) = lv;
                }
            }
        }
    }
}

// ---------------------------------------------------------------------------
// Attention: 8 queries per block (warp-per-query scores), fp32, bf16 hi/lo out
// ---------------------------------------------------------------------------
#define QBLK 8
__global__ void __launch_bounds__(256) attn_kernel(const float* __restrict__ qkv,
                                                   __nv_bfloat16* __restrict__ Ohi,
                                                   __nv_bfloat16* __restrict__ Olo)
{
    __shared__ float sc[QBLK][LSEQ];
    __shared__ float red[4][QBLK][DHEAD];
    __shared__ float sinv[QBLK];
    const int qb = blockIdx.x, h = blockIdx.y, b = blockIdx.z;
    const int tid = threadIdx.x, wid = tid >> 5, lane = tid & 31;
    const int cntmax = (qb + 1) * QBLK;
    const size_t rs = 3 * EMB;
    const int l = qb * QBLK + wid;

    const float* qrow = qkv + ((size_t)(b * LSEQ + l)) * rs + h * DHEAD;
    float4 q[16];
#pragma unroll
    for (int i = 0; i < 16; ++i) q[i] = *(const float4*)(qrow + 4 * i);

    float lmax = -1e30f;
    for (int m = lane; m < cntmax; m += 32) {
        const float* kr = qkv + ((size_t)(b * LSEQ + m)) * rs + EMB + h * DHEAD;
        float dot = 0.f;
#pragma unroll
        for (int i = 0; i < 16; ++i) {
            float4 kv = *(const float4*)(kr + 4 * i);
            dot = fmaf(q[i].x, kv.x, dot); dot = fmaf(q[i].y, kv.y, dot);
            dot = fmaf(q[i].z, kv.z, dot); dot = fmaf(q[i].w, kv.w, dot);
        }
        dot *= 0.125f;
        sc[wid][m] = dot;
        if (m <= l) lmax = fmaxf(lmax, dot);
    }
#pragma unroll
    for (int o = 16; o; o >>= 1) lmax = fmaxf(lmax, __shfl_xor_sync(~0u, lmax, o));
    float lsum = 0.f;
    for (int m = lane; m < cntmax; m += 32) {
        float e = (m <= l) ? __expf(sc[wid][m] - lmax) : 0.f;
        sc[wid][m] = e; lsum += e;
    }
#pragma unroll
    for (int o = 16; o; o >>= 1) lsum += __shfl_xor_sync(~0u, lsum, o);
    if (lane == 0) sinv[wid] = 1.f / lsum;
    __syncthreads();

    const int seg = tid >> 6, d = tid & 63;
    float acc[QBLK];
#pragma unroll
    for (int j = 0; j < QBLK; ++j) acc[j] = 0.f;
    for (int m = seg; m < cntmax; m += 4) {
        const float vv = qkv[((size_t)(b * LSEQ + m)) * rs + 2 * EMB + h * DHEAD + d];
#pragma unroll
        for (int j = 0; j < QBLK; ++j) acc[j] = fmaf(sc[j][m], vv, acc[j]);
    }
#pragma unroll
    for (int j = 0; j < QBLK; ++j) red[seg][j][d] = acc[j];
    __syncthreads();
#pragma unroll
    for (int t = 0; t < 2; ++t) {
        const int j = (tid >> 6) + t * 4;
        const float o4 = (red[0][j][d] + red[1][j][d] + red[2][j][d] + red[3][j][d]) * sinv[j];
        const int lq = qb * QBLK + j;
        const size_t oo = ((size_t)(b * LSEQ + lq)) * EMB + h * DHEAD + d;
        __nv_bfloat16 hi, lo; split_bf16(o4, hi, lo);
        Ohi[oo] = hi; Olo[oo] = lo;
    }
}

// ---------------------------------------------------------------------------
// Head
// ---------------------------------------------------------------------------
__global__ void head_kernel(const float* __restrict__ x, const float* __restrict__ w_out,
                            const float* __restrict__ b_out, float* __restrict__ out)
{
    __shared__ float red[256];
    const int idx = blockIdx.x, b = idx / KLEN, k = idx % KLEN, tid = threadIdx.x;
    const float* xr = x + ((size_t)(b * LSEQ + 2 * k)) * EMB;
    float acc = 0.f;
#pragma unroll
    for (int c = tid; c < EMB; c += 256) acc = fmaf(xr[c], w_out[c], acc);
    red[tid] = acc;
    __syncthreads();
    for (int off = 128; off > 0; off >>= 1) {
        if (tid < off) red[tid] += red[tid + off];
        __syncthreads();
    }
    if (tid == 0) out[idx] = red[0] + b_out[0];
}

// ---------------------------------------------------------------------------
// Launch
// ---------------------------------------------------------------------------
extern "C" void kernel_launch(void* const* d_in, const int* in_sizes, int n_in,
                              void* d_out, int out_size)
{
    const float* xs     = (const float*)d_in[0];
    const float* ys     = (const float*)d_in[1];
    const float* w_in   = (const float*)d_in[2];
    const float* b_in   = (const float*)d_in[3];
    const float* qkv_w  = (const float*)d_in[4];
    const float* qkv_b  = (const float*)d_in[5];
    const float* proj_w = (const float*)d_in[6];
    const float* proj_b = (const float*)d_in[7];
    const float* ln1_s  = (const float*)d_in[8];
    const float* ln1_b  = (const float*)d_in[9];
    const float* ln2_s  = (const float*)d_in[10];
    const float* ln2_b  = (const float*)d_in[11];
    const float* mlp_w1 = (const float*)d_in[12];
    const float* mlp_b1 = (const float*)d_in[13];
    const float* mlp_w2 = (const float*)d_in[14];
    const float* mlp_b2 = (const float*)d_in[15];
    const float* w_out  = (const float*)d_in[16];
    const float* b_out  = (const float*)d_in[17];
    float* out = (float*)d_out;

    float *x, *qkv;
    __nv_bfloat16 *hh, *hl, *ah, *al, *fh, *fl;
    __nv_bfloat16 *wqh, *wql, *wph, *wpl, *w1h, *w1l, *w2h, *w2l;
    cudaGetSymbolAddress((void**)&x,   g_x);
    cudaGetSymbolAddress((void**)&qkv, g_qkv);
    cudaGetSymbolAddress((void**)&hh,  g_hh);  cudaGetSymbolAddress((void**)&hl, g_hl);
    cudaGetSymbolAddress((void**)&ah,  g_ah);  cudaGetSymbolAddress((void**)&al, g_al);
    cudaGetSymbolAddress((void**)&fh,  g_fh);  cudaGetSymbolAddress((void**)&fl, g_fl);
    cudaGetSymbolAddress((void**)&wqh, g_wqh); cudaGetSymbolAddress((void**)&wql, g_wql);
    cudaGetSymbolAddress((void**)&wph, g_wph); cudaGetSymbolAddress((void**)&wpl, g_wpl);
    cudaGetSymbolAddress((void**)&w1h, g_w1h); cudaGetSymbolAddress((void**)&w1l, g_w1l);
    cudaGetSymbolAddress((void**)&w2h, g_w2h); cudaGetSymbolAddress((void**)&w2l, g_w2l);

    cudaFuncSetAttribute(gemm_mma<false, false, true,  false>, cudaFuncAttributeMaxDynamicSharedMemorySize, GEMM_SMEM);
    cudaFuncSetAttribute(gemm_mma<true,  false, true,  false>, cudaFuncAttributeMaxDynamicSharedMemorySize, GEMM_SMEM);
    cudaFuncSetAttribute(gemm_mma<false, true,  false, true >, cudaFuncAttributeMaxDynamicSharedMemorySize, GEMM_SMEM);

    const int M = MROWS;
    dim3 t32x8(32, 8);

    transpose_split<<<dim3(3 * EMB / 32, EMB / 32, NLAYER), t32x8>>>(qkv_w,  wqh, wql, EMB,   3 * EMB);
    transpose_split<<<dim3(EMB / 32,     EMB / 32, NLAYER), t32x8>>>(proj_w, wph, wpl, EMB,   EMB);
    transpose_split<<<dim3(FFDIM / 32,   EMB / 32, NLAYER), t32x8>>>(mlp_w1, w1h, w1l, EMB,   FFDIM);
    transpose_split<<<dim3(EMB / 32,   FFDIM / 32, NLAYER), t32x8>>>(mlp_w2, w2h, w2l, FFDIM, EMB);

    embed_kernel<<<dim3(EMB / 256, M), 256>>>(xs, ys, w_in, b_in);

    for (int lay = 0; lay < NLAYER; ++lay) {
        const float* qb  = qkv_b  + (size_t)lay * 3 * EMB;
        const float* pb  = proj_b + (size_t)lay * EMB;
        const float* s1  = ln1_s  + (size_t)lay * EMB;
        const float* c1  = ln1_b  + (size_t)lay * EMB;
        const float* s2  = ln2_s  + (size_t)lay * EMB;
        const float* c2  = ln2_b  + (size_t)lay * EMB;
        const float* bb1 = mlp_b1 + (size_t)lay * FFDIM;
        const float* bb2 = mlp_b2 + (size_t)lay * EMB;
        const __nv_bfloat16* lwqh = wqh + (size_t)lay * 3 * EMB * EMB;
        const __nv_bfloat16* lwql = wql + (size_t)lay * 3 * EMB * EMB;
        const __nv_bfloat16* lwph = wph + (size_t)lay * EMB * EMB;
        const __nv_bfloat16* lwpl = wpl + (size_t)lay * EMB * EMB;
        const __nv_bfloat16* lw1h = w1h + (size_t)lay * FFDIM * EMB;
        const __nv_bfloat16* lw1l = w1l + (size_t)lay * FFDIM * EMB;
        const __nv_bfloat16* lw2h = w2h + (size_t)lay * EMB * FFDIM;
        const __nv_bfloat16* lw2l = w2l + (size_t)lay * EMB * FFDIM;

        ln_kernel<<<M, 256>>>(x, s1, c1, hh, hl);
        gemm_mma<false, false, true, false><<<dim3(3 * EMB / 128, M / 128), 256, GEMM_SMEM>>>(
            hh, hl, lwqh, lwql, qb, nullptr, qkv, nullptr, nullptr, M, 3 * EMB, EMB);
        attn_kernel<<<dim3(LSEQ / QBLK, NHEAD, BATCH), 256>>>(qkv, ah, al);
        gemm_mma<true, false, true, false><<<dim3(EMB / 128, M / 128), 256, GEMM_SMEM>>>(
            ah, al, lwph, lwpl, pb, x, x, nullptr, nullptr, M, EMB, EMB);
        ln_kernel<<<M, 256>>>(x, s2, c2, hh, hl);
        gemm_mma<false, true, false, true><<<dim3(FFDIM / 128, M / 128), 256, GEMM_SMEM>>>(
            hh, hl, lw1h, lw1l, bb1, nullptr, nullptr, fh, fl, M, FFDIM, EMB);
        gemm_mma<true, false, true, false><<<dim3(EMB / 128, M / 128), 256, GEMM_SMEM>>>(
            fh, fl, lw2h, lw2l, bb2, x, x, nullptr, nullptr, M, EMB, FFDIM);
    }

    head_kernel<<<BATCH * KLEN, 256>>>(x, w_out, b_out, out);
}

// round 4
// speedup vs baseline: 3.3168x; 1.0579x over previous
#include <cuda_runtime.h>
#include <cuda_bf16.h>
#include <math.h>
#include <stdint.h>

#define BATCH 2
#define KLEN  512
#define LSEQ  1024
#define EMB   1024
#define NHEAD 16
#define DHEAD 64
#define NLAYER 12
#define FFDIM 4096
#define DIN   64
#define LN_EPS 1e-5f
#define MROWS (BATCH * LSEQ)   // 2048

// ---------------------------------------------------------------------------
// Scratch (device globals; allocation is forbidden)
// ---------------------------------------------------------------------------
__device__ float g_x   [MROWS * EMB];
__device__ float g_qkv [MROWS * 3 * EMB];
__device__ __nv_bfloat16 g_hh[MROWS * EMB];
__device__ __nv_bfloat16 g_hl[MROWS * EMB];
__device__ __nv_bfloat16 g_ah[MROWS * EMB];
__device__ __nv_bfloat16 g_al[MROWS * EMB];
__device__ __nv_bfloat16 g_fh[MROWS * FFDIM];
__device__ __nv_bfloat16 g_fl[MROWS * FFDIM];
// transposed + split weights: [layer][N][K]
__device__ __nv_bfloat16 g_wqh[NLAYER * 3 * EMB * EMB];
__device__ __nv_bfloat16 g_wql[NLAYER * 3 * EMB * EMB];
__device__ __nv_bfloat16 g_wph[NLAYER * EMB * EMB];
__device__ __nv_bfloat16 g_wpl[NLAYER * EMB * EMB];
__device__ __nv_bfloat16 g_w1h[NLAYER * FFDIM * EMB];
__device__ __nv_bfloat16 g_w1l[NLAYER * FFDIM * EMB];
__device__ __nv_bfloat16 g_w2h[NLAYER * EMB * FFDIM];
__device__ __nv_bfloat16 g_w2l[NLAYER * EMB * FFDIM];

// ---------------------------------------------------------------------------
// Helpers
// ---------------------------------------------------------------------------
__device__ __forceinline__ uint32_t smem_u32(const void* p) {
    uint32_t a;
    asm("{ .reg .u64 t; cvta.to.shared.u64 t, %1; cvt.u32.u64 %0, t; }" : "=r"(a) : "l"(p));
    return a;
}
__device__ __forceinline__ void cp_async16(uint32_t s, const void* g) {
    asm volatile("cp.async.cg.shared.global [%0], [%1], 16;" :: "r"(s), "l"(g));
}
#define CP_COMMIT() asm volatile("cp.async.commit_group;" ::: "memory")
#define CP_WAIT(n)  asm volatile("cp.async.wait_group %0;" :: "n"(n) : "memory")

__device__ __forceinline__ void ldsm4(uint32_t a, uint32_t& r0, uint32_t& r1,
                                      uint32_t& r2, uint32_t& r3) {
    asm volatile("ldmatrix.sync.aligned.m8n8.x4.shared.b16 {%0,%1,%2,%3}, [%4];"
                 : "=r"(r0), "=r"(r1), "=r"(r2), "=r"(r3) : "r"(a));
}
__device__ __forceinline__ void mma16816(float* d, const uint32_t* a,
                                         const uint32_t* b) {
    asm volatile(
        "mma.sync.aligned.m16n8k16.row.col.f32.bf16.bf16.f32 "
        "{%0,%1,%2,%3}, {%4,%5,%6,%7}, {%8,%9}, {%0,%1,%2,%3};"
        : "+f"(d[0]), "+f"(d[1]), "+f"(d[2]), "+f"(d[3])
        : "r"(a[0]), "r"(a[1]), "r"(a[2]), "r"(a[3]), "r"(b[0]), "r"(b[1]));
}
__device__ __forceinline__ void split_bf16(float v, __nv_bfloat16& hi, __nv_bfloat16& lo) {
    hi = __float2bfloat16(v);
    lo = __float2bfloat16(v - __bfloat162float(hi));
}

// ---------------------------------------------------------------------------
// Embed
// ---------------------------------------------------------------------------
__global__ void embed_kernel(const float* __restrict__ xs, const float* __restrict__ ys,
                             const float* __restrict__ w_in, const float* __restrict__ b_in)
{
    __shared__ float z[DIN];
    const int row = blockIdx.y, b = row / LSEQ, l = row % LSEQ, k = l >> 1;
    const int tid = threadIdx.x;
    if (tid < DIN) {
        float v;
        if ((l & 1) == 0) v = xs[(b * KLEN + k) * DIN + tid];
        else              v = (tid == 0) ? ys[b * KLEN + k] : 0.0f;
        z[tid] = v;
    }
    __syncthreads();
    const int n = blockIdx.x * blockDim.x + tid;
    float acc = b_in[n];
#pragma unroll 16
    for (int d = 0; d < DIN; ++d) acc += z[d] * w_in[d * EMB + n];
    g_x[row * EMB + n] = acc;
}

// ---------------------------------------------------------------------------
// LayerNorm -> bf16 hi/lo
// ---------------------------------------------------------------------------
__global__ void ln_kernel(const float* __restrict__ x,
                          const float* __restrict__ s, const float* __restrict__ bb,
                          __nv_bfloat16* __restrict__ ohi, __nv_bfloat16* __restrict__ olo)
{
    __shared__ float r1[256], r2[256], stats[2];
    const int row = blockIdx.x, tid = threadIdx.x;
    const float* xr = x + (size_t)row * EMB;
    float sum = 0.f, sq = 0.f;
#pragma unroll
    for (int c = tid; c < EMB; c += 256) { float v = xr[c]; sum += v; sq += v * v; }
    r1[tid] = sum; r2[tid] = sq;
    __syncthreads();
    for (int off = 128; off > 0; off >>= 1) {
        if (tid < off) { r1[tid] += r1[tid + off]; r2[tid] += r2[tid + off]; }
        __syncthreads();
    }
    if (tid == 0) {
        float m = r1[0] * (1.0f / EMB);
        float v = r2[0] * (1.0f / EMB) - m * m;
        stats[0] = m; stats[1] = rsqrtf(v + LN_EPS);
    }
    __syncthreads();
    const float m = stats[0], rstd = stats[1];
#pragma unroll
    for (int c = tid; c < EMB; c += 256) {
        float v = (xr[c] - m) * rstd * s[c] + bb[c];
        __nv_bfloat16 hi, lo; split_bf16(v, hi, lo);
        ohi[(size_t)row * EMB + c] = hi;
        olo[(size_t)row * EMB + c] = lo;
    }
}

// ---------------------------------------------------------------------------
// Weight transpose + split: W[layer][K][N] -> T[layer][N][K] (hi, lo)
// ---------------------------------------------------------------------------
__global__ void transpose_split(const float* __restrict__ W,
                                __nv_bfloat16* __restrict__ Th, __nv_bfloat16* __restrict__ Tl,
                                int K, int N)
{
    __shared__ float t[32][33];
    const int lay = blockIdx.z;
    const float* Ws = W + (size_t)lay * K * N;
    __nv_bfloat16* Ths = Th + (size_t)lay * K * N;
    __nv_bfloat16* Tls = Tl + (size_t)lay * K * N;
    const int n0 = blockIdx.x * 32, k0 = blockIdx.y * 32;
    for (int i = threadIdx.y; i < 32; i += 8)
        t[i][threadIdx.x] = Ws[(size_t)(k0 + i) * N + n0 + threadIdx.x];
    __syncthreads();
    for (int i = threadIdx.y; i < 32; i += 8) {
        float v = t[threadIdx.x][i];
        __nv_bfloat16 hi, lo; split_bf16(v, hi, lo);
        size_t o = (size_t)(n0 + i) * K + k0 + threadIdx.x;
        Ths[o] = hi; Tls[o] = lo;
    }
}

// ---------------------------------------------------------------------------
// Split-bf16 GEMM via mma.sync (m16n8k16). 128x128 CTA tile, 512 threads,
// 16 warps in 4x4 grid, warp tile 32x32. 3-stage cp.async pipeline.
// smem stage: Ah,Al,Bh,Bl each 128 rows x 80B. Term-major MMA order (no RAW
// back-to-back on the same accumulator). ldmatrix.x4 fragment loads.
// ---------------------------------------------------------------------------
#define RSTRIDE 80
#define MAT_BYTES (128 * RSTRIDE)          // 10240
#define STAGE_BYTES (4 * MAT_BYTES)        // 40960
#define NSTAGE 3
#define GEMM_SMEM (NSTAGE * STAGE_BYTES)   // 122880

template <bool RES, bool GELU, bool OUT_F32, bool OUT_BF16>
__global__ void __launch_bounds__(512, 1) gemm_mma(
    const __nv_bfloat16* __restrict__ Ah, const __nv_bfloat16* __restrict__ Al,
    const __nv_bfloat16* __restrict__ Bh, const __nv_bfloat16* __restrict__ Bl,
    const float* __restrict__ bias, const float* __restrict__ Rres,
    float* __restrict__ C, __nv_bfloat16* __restrict__ Chi, __nv_bfloat16* __restrict__ Clo,
    int M, int N, int K)
{
    extern __shared__ char smem[];
    const uint32_t sbase = smem_u32(smem);
    const int tid = threadIdx.x, wid = tid >> 5, lane = tid & 31;
    const int m0 = blockIdx.y * 128, n0 = blockIdx.x * 128;
    const int wm = wid & 3, wn = wid >> 2;           // warp tile: 32(m) x 32(n)
    const int g = lane >> 2, q = lane & 3;

    // cp.async mapping: thread -> (row 0..127, 16B chunk 0..3)
    const int lrow = tid >> 2;
    const int lch  = tid & 3;
    const uint32_t soff = (uint32_t)(lrow * RSTRIDE + lch * 16);

    // ldmatrix per-lane address offsets (within a stage buffer)
    const uint32_t aoff = (uint32_t)((wm * 32 + (lane & 15)) * RSTRIDE + (lane >> 4) * 16);
    const uint32_t boff = (uint32_t)((wn * 32 + (lane >> 4) * 8 + (lane & 7)) * RSTRIDE
                                     + ((lane >> 3) & 1) * 16);

    float acc[2][4][4];
#pragma unroll
    for (int i = 0; i < 2; ++i)
#pragma unroll
        for (int j = 0; j < 4; ++j)
#pragma unroll
            for (int r = 0; r < 4; ++r) acc[i][j][r] = 0.f;

    const int CH = K >> 5;

    auto load_stage = [&](int c, int buf) {
        const int k0 = c << 5;
        const uint32_t sb = sbase + buf * STAGE_BYTES + soff;
        const size_t ga = (size_t)(m0 + lrow) * K + k0 + lch * 8;
        const size_t gb = (size_t)(n0 + lrow) * K + k0 + lch * 8;
        cp_async16(sb,                 Ah + ga);
        cp_async16(sb + MAT_BYTES,     Al + ga);
        cp_async16(sb + 2 * MAT_BYTES, Bh + gb);
        cp_async16(sb + 3 * MAT_BYTES, Bl + gb);
    };

    load_stage(0, 0); CP_COMMIT();
    load_stage(1, 1); CP_COMMIT();

    int buf = 0;
    for (int c = 0; c < CH; ++c) {
        CP_WAIT(1);
        __syncthreads();
        if (c + 2 < CH) { load_stage(c + 2, (buf + 2) % NSTAGE); CP_COMMIT(); }
        else            { CP_COMMIT(); }   // keep group count in step

        const uint32_t sA = sbase + buf * STAGE_BYTES;
        const uint32_t sB = sA + 2 * MAT_BYTES;
#pragma unroll
        for (int ks = 0; ks < 2; ++ks) {
            uint32_t Ahf[2][4], Alf[2][4], Bhf[4][2], Blf[4][2];
#pragma unroll
            for (int mt = 0; mt < 2; ++mt) {
                const uint32_t aa = sA + aoff + mt * 16 * RSTRIDE + ks * 32;
                ldsm4(aa,             Ahf[mt][0], Ahf[mt][1], Ahf[mt][2], Ahf[mt][3]);
                ldsm4(aa + MAT_BYTES, Alf[mt][0], Alf[mt][1], Alf[mt][2], Alf[mt][3]);
            }
#pragma unroll
            for (int p = 0; p < 2; ++p) {
                const uint32_t ba = sB + boff + p * 16 * RSTRIDE + ks * 32;
                ldsm4(ba,             Bhf[2*p][0], Bhf[2*p][1], Bhf[2*p+1][0], Bhf[2*p+1][1]);
                ldsm4(ba + MAT_BYTES, Blf[2*p][0], Blf[2*p][1], Blf[2*p+1][0], Blf[2*p+1][1]);
            }
            // term-major: consecutive MMAs hit different accumulators
#pragma unroll
            for (int mt = 0; mt < 2; ++mt)
#pragma unroll
                for (int nt = 0; nt < 4; ++nt)
                    mma16816(acc[mt][nt], Ahf[mt], Bhf[nt]);
#pragma unroll
            for (int mt = 0; mt < 2; ++mt)
#pragma unroll
                for (int nt = 0; nt < 4; ++nt)
                    mma16816(acc[mt][nt], Ahf[mt], Blf[nt]);
#pragma unroll
            for (int mt = 0; mt < 2; ++mt)
#pragma unroll
                for (int nt = 0; nt < 4; ++nt)
                    mma16816(acc[mt][nt], Alf[mt], Bhf[nt]);
        }
        __syncthreads();
        buf = (buf + 1) % NSTAGE;
    }

    // epilogue: direct stores (float2 / bf16x2)
#pragma unroll
    for (int nt = 0; nt < 4; ++nt) {
        const int col = n0 + wn * 32 + nt * 8 + q * 2;
        const float bia0 = bias[col], bia1 = bias[col + 1];
#pragma unroll
        for (int mt = 0; mt < 2; ++mt) {
#pragma unroll
            for (int h2 = 0; h2 < 2; ++h2) {
                const int row = m0 + wm * 32 + mt * 16 + g + h2 * 8;
                float v0 = acc[mt][nt][h2 * 2 + 0] + bia0;
                float v1 = acc[mt][nt][h2 * 2 + 1] + bia1;
                const size_t o = (size_t)row * N + col;
                if (RES) { v0 += Rres[o]; v1 += Rres[o + 1]; }
                if (GELU) {
                    v0 = 0.5f * v0 * (1.0f + erff(v0 * 0.70710678118654752f));
                    v1 = 0.5f * v1 * (1.0f + erff(v1 * 0.70710678118654752f));
                }
                if (OUT_F32) { float2 fv = {v0, v1}; *(float2*)(C + o) = fv; }
                if (OUT_BF16) {
                    __nv_bfloat16 h0, l0, h1, l1;
                    split_bf16(v0, h0, l0); split_bf16(v1, h1, l1);
                    __nv_bfloat162 hv; hv.x = h0; hv.y = h1;
                    __nv_bfloat162 lv; lv.x = l0; lv.y = l1;
                    *(__nv_bfloat162*)(Chi + o) = hv;
                    *(__nv_bfloat162*)(Clo + o) = lv;
                }
            }
        }
    }
}

// ---------------------------------------------------------------------------
// Attention: 8 queries per block (warp-per-query scores), fp32, bf16 hi/lo out
// ---------------------------------------------------------------------------
#define QBLK 8
__global__ void __launch_bounds__(256) attn_kernel(const float* __restrict__ qkv,
                                                   __nv_bfloat16* __restrict__ Ohi,
                                                   __nv_bfloat16* __restrict__ Olo)
{
    __shared__ float sc[QBLK][LSEQ];
    __shared__ float red[4][QBLK][DHEAD];
    __shared__ float sinv[QBLK];
    const int qb = blockIdx.x, h = blockIdx.y, b = blockIdx.z;
    const int tid = threadIdx.x, wid = tid >> 5, lane = tid & 31;
    const int cntmax = (qb + 1) * QBLK;
    const size_t rs = 3 * EMB;
    const int l = qb * QBLK + wid;

    const float* qrow = qkv + ((size_t)(b * LSEQ + l)) * rs + h * DHEAD;
    float4 q[16];
#pragma unroll
    for (int i = 0; i < 16; ++i) q[i] = *(const float4*)(qrow + 4 * i);

    float lmax = -1e30f;
    for (int m = lane; m < cntmax; m += 32) {
        const float* kr = qkv + ((size_t)(b * LSEQ + m)) * rs + EMB + h * DHEAD;
        float dot = 0.f;
#pragma unroll
        for (int i = 0; i < 16; ++i) {
            float4 kv = *(const float4*)(kr + 4 * i);
            dot = fmaf(q[i].x, kv.x, dot); dot = fmaf(q[i].y, kv.y, dot);
            dot = fmaf(q[i].z, kv.z, dot); dot = fmaf(q[i].w, kv.w, dot);
        }
        dot *= 0.125f;
        sc[wid][m] = dot;
        if (m <= l) lmax = fmaxf(lmax, dot);
    }
#pragma unroll
    for (int o = 16; o; o >>= 1) lmax = fmaxf(lmax, __shfl_xor_sync(~0u, lmax, o));
    float lsum = 0.f;
    for (int m = lane; m < cntmax; m += 32) {
        float e = (m <= l) ? __expf(sc[wid][m] - lmax) : 0.f;
        sc[wid][m] = e; lsum += e;
    }
#pragma unroll
    for (int o = 16; o; o >>= 1) lsum += __shfl_xor_sync(~0u, lsum, o);
    if (lane == 0) sinv[wid] = 1.f / lsum;
    __syncthreads();

    const int seg = tid >> 6, d = tid & 63;
    float acc[QBLK];
#pragma unroll
    for (int j = 0; j < QBLK; ++j) acc[j] = 0.f;
    for (int m = seg; m < cntmax; m += 4) {
        const float vv = qkv[((size_t)(b * LSEQ + m)) * rs + 2 * EMB + h * DHEAD + d];
#pragma unroll
        for (int j = 0; j < QBLK; ++j) acc[j] = fmaf(sc[j][m], vv, acc[j]);
    }
#pragma unroll
    for (int j = 0; j < QBLK; ++j) red[seg][j][d] = acc[j];
    __syncthreads();
#pragma unroll
    for (int t = 0; t < 2; ++t) {
        const int j = (tid >> 6) + t * 4;
        const float o4 = (red[0][j][d] + red[1][j][d] + red[2][j][d] + red[3][j][d]) * sinv[j];
        const int lq = qb * QBLK + j;
        const size_t oo = ((size_t)(b * LSEQ + lq)) * EMB + h * DHEAD + d;
        __nv_bfloat16 hi, lo; split_bf16(o4, hi, lo);
        Ohi[oo] = hi; Olo[oo] = lo;
    }
}

// ---------------------------------------------------------------------------
// Head
// ---------------------------------------------------------------------------
__global__ void head_kernel(const float* __restrict__ x, const float* __restrict__ w_out,
                            const float* __restrict__ b_out, float* __restrict__ out)
{
    __shared__ float red[256];
    const int idx = blockIdx.x, b = idx / KLEN, k = idx % KLEN, tid = threadIdx.x;
    const float* xr = x + ((size_t)(b * LSEQ + 2 * k)) * EMB;
    float acc = 0.f;
#pragma unroll
    for (int c = tid; c < EMB; c += 256) acc = fmaf(xr[c], w_out[c], acc);
    red[tid] = acc;
    __syncthreads();
    for (int off = 128; off > 0; off >>= 1) {
        if (tid < off) red[tid] += red[tid + off];
        __syncthreads();
    }
    if (tid == 0) out[idx] = red[0] + b_out[0];
}

// ---------------------------------------------------------------------------
// Launch
// ---------------------------------------------------------------------------
extern "C" void kernel_launch(void* const* d_in, const int* in_sizes, int n_in,
                              void* d_out, int out_size)
{
    const float* xs     = (const float*)d_in[0];
    const float* ys     = (const float*)d_in[1];
    const float* w_in   = (const float*)d_in[2];
    const float* b_in   = (const float*)d_in[3];
    const float* qkv_w  = (const float*)d_in[4];
    const float* qkv_b  = (const float*)d_in[5];
    const float* proj_w = (const float*)d_in[6];
    const float* proj_b = (const float*)d_in[7];
    const float* ln1_s  = (const float*)d_in[8];
    const float* ln1_b  = (const float*)d_in[9];
    const float* ln2_s  = (const float*)d_in[10];
    const float* ln2_b  = (const float*)d_in[11];
    const float* mlp_w1 = (const float*)d_in[12];
    const float* mlp_b1 = (const float*)d_in[13];
    const float* mlp_w2 = (const float*)d_in[14];
    const float* mlp_b2 = (const float*)d_in[15];
    const float* w_out  = (const float*)d_in[16];
    const float* b_out  = (const float*)d_in[17];
    float* out = (float*)d_out;

    float *x, *qkv;
    __nv_bfloat16 *hh, *hl, *ah, *al, *fh, *fl;
    __nv_bfloat16 *wqh, *wql, *wph, *wpl, *w1h, *w1l, *w2h, *w2l;
    cudaGetSymbolAddress((void**)&x,   g_x);
    cudaGetSymbolAddress((void**)&qkv, g_qkv);
    cudaGetSymbolAddress((void**)&hh,  g_hh);  cudaGetSymbolAddress((void**)&hl, g_hl);
    cudaGetSymbolAddress((void**)&ah,  g_ah);  cudaGetSymbolAddress((void**)&al, g_al);
    cudaGetSymbolAddress((void**)&fh,  g_fh);  cudaGetSymbolAddress((void**)&fl, g_fl);
    cudaGetSymbolAddress((void**)&wqh, g_wqh); cudaGetSymbolAddress((void**)&wql, g_wql);
    cudaGetSymbolAddress((void**)&wph, g_wph); cudaGetSymbolAddress((void**)&wpl, g_wpl);
    cudaGetSymbolAddress((void**)&w1h, g_w1h); cudaGetSymbolAddress((void**)&w1l, g_w1l);
    cudaGetSymbolAddress((void**)&w2h, g_w2h); cudaGetSymbolAddress((void**)&w2l, g_w2l);

    cudaFuncSetAttribute(gemm_mma<false, false, true,  false>, cudaFuncAttributeMaxDynamicSharedMemorySize, GEMM_SMEM);
    cudaFuncSetAttribute(gemm_mma<true,  false, true,  false>, cudaFuncAttributeMaxDynamicSharedMemorySize, GEMM_SMEM);
    cudaFuncSetAttribute(gemm_mma<false, true,  false, true >, cudaFuncAttributeMaxDynamicSharedMemorySize, GEMM_SMEM);

    const int M = MROWS;
    dim3 t32x8(32, 8);

    transpose_split<<<dim3(3 * EMB / 32, EMB / 32, NLAYER), t32x8>>>(qkv_w,  wqh, wql, EMB,   3 * EMB);
    transpose_split<<<dim3(EMB / 32,     EMB / 32, NLAYER), t32x8>>>(proj_w, wph, wpl, EMB,   EMB);
    transpose_split<<<dim3(FFDIM / 32,   EMB / 32, NLAYER), t32x8>>>(mlp_w1, w1h, w1l, EMB,   FFDIM);
    transpose_split<<<dim3(EMB / 32,   FFDIM / 32, NLAYER), t32x8>>>(mlp_w2, w2h, w2l, FFDIM, EMB);

    embed_kernel<<<dim3(EMB / 256, M), 256>>>(xs, ys, w_in, b_in);

    for (int lay = 0; lay < NLAYER; ++lay) {
        const float* qb  = qkv_b  + (size_t)lay * 3 * EMB;
        const float* pb  = proj_b + (size_t)lay * EMB;
        const float* s1  = ln1_s  + (size_t)lay * EMB;
        const float* c1  = ln1_b  + (size_t)lay * EMB;
        const float* s2  = ln2_s  + (size_t)lay * EMB;
        const float* c2  = ln2_b  + (size_t)lay * EMB;
        const float* bb1 = mlp_b1 + (size_t)lay * FFDIM;
        const float* bb2 = mlp_b2 + (size_t)lay * EMB;
        const __nv_bfloat16* lwqh = wqh + (size_t)lay * 3 * EMB * EMB;
        const __nv_bfloat16* lwql = wql + (size_t)lay * 3 * EMB * EMB;
        const __nv_bfloat16* lwph = wph + (size_t)lay * EMB * EMB;
        const __nv_bfloat16* lwpl = wpl + (size_t)lay * EMB * EMB;
        const __nv_bfloat16* lw1h = w1h + (size_t)lay * FFDIM * EMB;
        const __nv_bfloat16* lw1l = w1l + (size_t)lay * FFDIM * EMB;
        const __nv_bfloat16* lw2h = w2h + (size_t)lay * EMB * FFDIM;
        const __nv_bfloat16* lw2l = w2l + (size_t)lay * EMB * FFDIM;

        ln_kernel<<<M, 256>>>(x, s1, c1, hh, hl);
        gemm_mma<false, false, true, false><<<dim3(3 * EMB / 128, M / 128), 512, GEMM_SMEM>>>(
            hh, hl, lwqh, lwql, qb, nullptr, qkv, nullptr, nullptr, M, 3 * EMB, EMB);
        attn_kernel<<<dim3(LSEQ / QBLK, NHEAD, BATCH), 256>>>(qkv, ah, al);
        gemm_mma<true, false, true, false><<<dim3(EMB / 128, M / 128), 512, GEMM_SMEM>>>(
            ah, al, lwph, lwpl, pb, x, x, nullptr, nullptr, M, EMB, EMB);
        ln_kernel<<<M, 256>>>(x, s2, c2, hh, hl);
        gemm_mma<false, true, false, true><<<dim3(FFDIM / 128, M / 128), 512, GEMM_SMEM>>>(
            hh, hl, lw1h, lw1l, bb1, nullptr, nullptr, fh, fl, M, FFDIM, EMB);
        gemm_mma<true, false, true, false><<<dim3(EMB / 128, M / 128), 512, GEMM_SMEM>>>(
            fh, fl, lw2h, lw2l, bb2, x, x, nullptr, nullptr, M, EMB, FFDIM);
    }

    head_kernel<<<BATCH * KLEN, 256>>>(x, w_out, b_out, out);
}

// round 5
// speedup vs baseline: 3.8375x; 1.1570x over previous
#include <cuda_runtime.h>
#include <cuda_fp16.h>
#include <math.h>
#include <stdint.h>

#define BATCH 2
#define KLEN  512
#define LSEQ  1024
#define EMB   1024
#define NHEAD 16
#define DHEAD 64
#define NLAYER 12
#define FFDIM 4096
#define DIN   64
#define LN_EPS 1e-5f
#define MROWS (BATCH * LSEQ)   // 2048

// ---------------------------------------------------------------------------
// Scratch (device globals; allocation is forbidden)
// ---------------------------------------------------------------------------
__device__ float g_x   [MROWS * EMB];
__device__ float g_qkv [MROWS * 3 * EMB];
__device__ __half g_h  [MROWS * EMB];      // ln out (fp16)
__device__ __half g_a  [MROWS * EMB];      // attn out (fp16)
__device__ __half g_f  [MROWS * FFDIM];    // mlp hidden (fp16)
// transposed + split weights: [layer][N][K], fp16 hi + lo
__device__ __half g_wqh[NLAYER * 3 * EMB * EMB];
__device__ __half g_wql[NLAYER * 3 * EMB * EMB];
__device__ __half g_wph[NLAYER * EMB * EMB];
__device__ __half g_wpl[NLAYER * EMB * EMB];
__device__ __half g_w1h[NLAYER * FFDIM * EMB];
__device__ __half g_w1l[NLAYER * FFDIM * EMB];
__device__ __half g_w2h[NLAYER * EMB * FFDIM];
__device__ __half g_w2l[NLAYER * EMB * FFDIM];

// ---------------------------------------------------------------------------
// Helpers
// ---------------------------------------------------------------------------
__device__ __forceinline__ uint32_t smem_u32(const void* p) {
    uint32_t a;
    asm("{ .reg .u64 t; cvta.to.shared.u64 t, %1; cvt.u32.u64 %0, t; }" : "=r"(a) : "l"(p));
    return a;
}
__device__ __forceinline__ void cp_async16(uint32_t s, const void* g) {
    asm volatile("cp.async.cg.shared.global [%0], [%1], 16;" :: "r"(s), "l"(g));
}
#define CP_COMMIT() asm volatile("cp.async.commit_group;" ::: "memory")
#define CP_WAIT(n)  asm volatile("cp.async.wait_group %0;" :: "n"(n) : "memory")

__device__ __forceinline__ void ldsm4(uint32_t a, uint32_t& r0, uint32_t& r1,
                                      uint32_t& r2, uint32_t& r3) {
    asm volatile("ldmatrix.sync.aligned.m8n8.x4.shared.b16 {%0,%1,%2,%3}, [%4];"
                 : "=r"(r0), "=r"(r1), "=r"(r2), "=r"(r3) : "r"(a));
}
__device__ __forceinline__ void mma16816(float* d, const uint32_t* a,
                                         const uint32_t* b) {
    asm volatile(
        "mma.sync.aligned.m16n8k16.row.col.f32.f16.f16.f32 "
        "{%0,%1,%2,%3}, {%4,%5,%6,%7}, {%8,%9}, {%0,%1,%2,%3};"
        : "+f"(d[0]), "+f"(d[1]), "+f"(d[2]), "+f"(d[3])
        : "r"(a[0]), "r"(a[1]), "r"(a[2]), "r"(a[3]), "r"(b[0]), "r"(b[1]));
}
__device__ __forceinline__ void split_f16(float v, __half& hi, __half& lo) {
    hi = __float2half_rn(v);
    lo = __float2half_rn(v - __half2float(hi));
}

// ---------------------------------------------------------------------------
// Fused weight transpose + split (ONE launch): W[K][N] -> T[N][K] fp16 hi/lo
// grid (12288, NLAYER), block (32,8)
// tile map: [0,3072) qkv | [3072,4096) proj | [4096,8192) mlp1 | [8192,12288) mlp2
// ---------------------------------------------------------------------------
__global__ void transpose_split_all(
    const float* __restrict__ qkv_w, const float* __restrict__ proj_w,
    const float* __restrict__ mlp_w1, const float* __restrict__ mlp_w2,
    __half* __restrict__ wqh, __half* __restrict__ wql,
    __half* __restrict__ wph, __half* __restrict__ wpl,
    __half* __restrict__ w1h, __half* __restrict__ w1l,
    __half* __restrict__ w2h, __half* __restrict__ w2l)
{
    __shared__ float t[32][33];
    const int lay = blockIdx.y;
    int tt = blockIdx.x;
    const float* W; __half *Th, *Tl; int K, N;
    if (tt < 3072)      { W = qkv_w;  Th = wqh; Tl = wql; K = EMB;   N = 3 * EMB; }
    else if (tt < 4096) { W = proj_w; Th = wph; Tl = wpl; K = EMB;   N = EMB;   tt -= 3072; }
    else if (tt < 8192) { W = mlp_w1; Th = w1h; Tl = w1l; K = EMB;   N = FFDIM; tt -= 4096; }
    else                { W = mlp_w2; Th = w2h; Tl = w2l; K = FFDIM; N = EMB;   tt -= 8192; }
    const int ntx = N >> 5;
    const int n0 = (tt % ntx) * 32, k0 = (tt / ntx) * 32;
    const float* Ws = W + (size_t)lay * K * N;
    __half* Ths = Th + (size_t)lay * K * N;
    __half* Tls = Tl + (size_t)lay * K * N;
    for (int i = threadIdx.y; i < 32; i += 8)
        t[i][threadIdx.x] = Ws[(size_t)(k0 + i) * N + n0 + threadIdx.x];
    __syncthreads();
    for (int i = threadIdx.y; i < 32; i += 8) {
        float v = t[threadIdx.x][i];
        __half hi, lo; split_f16(v, hi, lo);
        size_t o = (size_t)(n0 + i) * K + k0 + threadIdx.x;
        Ths[o] = hi; Tls[o] = lo;
    }
}

// ---------------------------------------------------------------------------
// Embed
// ---------------------------------------------------------------------------
__global__ void embed_kernel(const float* __restrict__ xs, const float* __restrict__ ys,
                             const float* __restrict__ w_in, const float* __restrict__ b_in)
{
    __shared__ float z[DIN];
    const int row = blockIdx.y, b = row / LSEQ, l = row % LSEQ, k = l >> 1;
    const int tid = threadIdx.x;
    if (tid < DIN) {
        float v;
        if ((l & 1) == 0) v = xs[(b * KLEN + k) * DIN + tid];
        else              v = (tid == 0) ? ys[b * KLEN + k] : 0.0f;
        z[tid] = v;
    }
    __syncthreads();
    const int n = blockIdx.x * blockDim.x + tid;
    float acc = b_in[n];
#pragma unroll 16
    for (int d = 0; d < DIN; ++d) acc += z[d] * w_in[d * EMB + n];
    g_x[row * EMB + n] = acc;
}

// ---------------------------------------------------------------------------
// LayerNorm -> fp16
// ---------------------------------------------------------------------------
__global__ void ln_kernel(const float* __restrict__ x,
                          const float* __restrict__ s, const float* __restrict__ bb,
                          __half* __restrict__ oh)
{
    __shared__ float r1[256], r2[256], stats[2];
    const int row = blockIdx.x, tid = threadIdx.x;
    const float* xr = x + (size_t)row * EMB;
    float sum = 0.f, sq = 0.f;
#pragma unroll
    for (int c = tid; c < EMB; c += 256) { float v = xr[c]; sum += v; sq += v * v; }
    r1[tid] = sum; r2[tid] = sq;
    __syncthreads();
    for (int off = 128; off > 0; off >>= 1) {
        if (tid < off) { r1[tid] += r1[tid + off]; r2[tid] += r2[tid + off]; }
        __syncthreads();
    }
    if (tid == 0) {
        float m = r1[0] * (1.0f / EMB);
        float v = r2[0] * (1.0f / EMB) - m * m;
        stats[0] = m; stats[1] = rsqrtf(v + LN_EPS);
    }
    __syncthreads();
    const float m = stats[0], rstd = stats[1];
#pragma unroll
    for (int c = tid; c < EMB; c += 256) {
        float v = (xr[c] - m) * rstd * s[c] + bb[c];
        oh[(size_t)row * EMB + c] = __float2half_rn(v);
    }
}

// ---------------------------------------------------------------------------
// 2-term fp16 GEMM via mma.sync: C = A_fp16[M,K] @ (Bh+Bl)[N,K]^T (+bias,...)
// 128x128 CTA tile, 512 threads, 16 warps 4x4, warp tile 32x32.
// 4-stage cp.async pipeline, ONE barrier per k-chunk(32).
// smem stage: A, Bh, Bl each 128 x 80B = 30720B; 4 stages = 122880B.
// ---------------------------------------------------------------------------
#define RSTRIDE 80
#define MAT_BYTES (128 * RSTRIDE)          // 10240
#define STAGE_BYTES (3 * MAT_BYTES)        // 30720
#define NSTAGE 4
#define GEMM_SMEM (NSTAGE * STAGE_BYTES)   // 122880

template <bool RES, bool GELU, bool OUT_F32, bool OUT_F16>
__global__ void __launch_bounds__(512, 1) gemm_mma(
    const __half* __restrict__ A,
    const __half* __restrict__ Bh, const __half* __restrict__ Bl,
    const float* __restrict__ bias, const float* __restrict__ Rres,
    float* __restrict__ C, __half* __restrict__ Ch,
    int M, int N, int K)
{
    extern __shared__ char smem[];
    const uint32_t sbase = smem_u32(smem);
    const int tid = threadIdx.x, wid = tid >> 5, lane = tid & 31;
    const int m0 = blockIdx.y * 128, n0 = blockIdx.x * 128;
    const int wm = wid & 3, wn = wid >> 2;           // warp tile: 32(m) x 32(n)
    const int g = lane >> 2, q = lane & 3;

    // cp.async mapping: thread -> (row 0..127, 16B chunk 0..3)
    const int lrow = tid >> 2;
    const int lch  = tid & 3;
    const uint32_t soff = (uint32_t)(lrow * RSTRIDE + lch * 16);

    // ldmatrix per-lane address offsets (within a stage buffer)
    const uint32_t aoff = (uint32_t)((wm * 32 + (lane & 15)) * RSTRIDE + (lane >> 4) * 16);
    const uint32_t boff = (uint32_t)((wn * 32 + (lane >> 4) * 8 + (lane & 7)) * RSTRIDE
                                     + ((lane >> 3) & 1) * 16);

    float acc[2][4][4];
#pragma unroll
    for (int i = 0; i < 2; ++i)
#pragma unroll
        for (int j = 0; j < 4; ++j)
#pragma unroll
            for (int r = 0; r < 4; ++r) acc[i][j][r] = 0.f;

    const int CH = K >> 5;

    auto load_stage = [&](int c) {
        const int k0 = c << 5;
        const uint32_t sb = sbase + (c & (NSTAGE - 1)) * STAGE_BYTES + soff;
        const size_t ga = (size_t)(m0 + lrow) * K + k0 + lch * 8;
        const size_t gb = (size_t)(n0 + lrow) * K + k0 + lch * 8;
        cp_async16(sb,                 A  + ga);
        cp_async16(sb + MAT_BYTES,     Bh + gb);
        cp_async16(sb + 2 * MAT_BYTES, Bl + gb);
    };

    load_stage(0); CP_COMMIT();
    load_stage(1); CP_COMMIT();
    load_stage(2); CP_COMMIT();

    for (int c = 0; c < CH; ++c) {
        CP_WAIT(2);
        __syncthreads();

        const uint32_t sA = sbase + (c & (NSTAGE - 1)) * STAGE_BYTES;
        const uint32_t sB = sA + MAT_BYTES;
#pragma unroll
        for (int ks = 0; ks < 2; ++ks) {
            uint32_t Af[2][4], Bhf[4][2], Blf[4][2];
#pragma unroll
            for (int mt = 0; mt < 2; ++mt) {
                const uint32_t aa = sA + aoff + mt * 16 * RSTRIDE + ks * 32;
                ldsm4(aa, Af[mt][0], Af[mt][1], Af[mt][2], Af[mt][3]);
            }
#pragma unroll
            for (int p = 0; p < 2; ++p) {
                const uint32_t ba = sB + boff + p * 16 * RSTRIDE + ks * 32;
                ldsm4(ba,             Bhf[2*p][0], Bhf[2*p][1], Bhf[2*p+1][0], Bhf[2*p+1][1]);
                ldsm4(ba + MAT_BYTES, Blf[2*p][0], Blf[2*p][1], Blf[2*p+1][0], Blf[2*p+1][1]);
            }
            // term-major: consecutive MMAs hit different accumulators
#pragma unroll
            for (int mt = 0; mt < 2; ++mt)
#pragma unroll
                for (int nt = 0; nt < 4; ++nt)
                    mma16816(acc[mt][nt], Af[mt], Bhf[nt]);
#pragma unroll
            for (int mt = 0; mt < 2; ++mt)
#pragma unroll
                for (int nt = 0; nt < 4; ++nt)
                    mma16816(acc[mt][nt], Af[mt], Blf[nt]);
        }
        if (c + 3 < CH) load_stage(c + 3);
        CP_COMMIT();
    }

    // epilogue
#pragma unroll
    for (int nt = 0; nt < 4; ++nt) {
        const int col = n0 + wn * 32 + nt * 8 + q * 2;
        const float bia0 = bias[col], bia1 = bias[col + 1];
#pragma unroll
        for (int mt = 0; mt < 2; ++mt) {
#pragma unroll
            for (int h2 = 0; h2 < 2; ++h2) {
                const int row = m0 + wm * 32 + mt * 16 + g + h2 * 8;
                float v0 = acc[mt][nt][h2 * 2 + 0] + bia0;
                float v1 = acc[mt][nt][h2 * 2 + 1] + bia1;
                const size_t o = (size_t)row * N + col;
                if (RES) { v0 += Rres[o]; v1 += Rres[o + 1]; }
                if (GELU) {
                    v0 = 0.5f * v0 * (1.0f + erff(v0 * 0.70710678118654752f));
                    v1 = 0.5f * v1 * (1.0f + erff(v1 * 0.70710678118654752f));
                }
                if (OUT_F32) { float2 fv = {v0, v1}; *(float2*)(C + o) = fv; }
                if (OUT_F16) {
                    __half2 hv; hv.x = __float2half_rn(v0); hv.y = __float2half_rn(v1);
                    *(__half2*)(Ch + o) = hv;
                }
            }
        }
    }
}

// ---------------------------------------------------------------------------
// Attention: 8 queries per block (warp-per-query scores), fp32, fp16 out
// ---------------------------------------------------------------------------
#define QBLK 8
__global__ void __launch_bounds__(256) attn_kernel(const float* __restrict__ qkv,
                                                   __half* __restrict__ Oh)
{
    __shared__ float sc[QBLK][LSEQ];
    __shared__ float red[4][QBLK][DHEAD];
    __shared__ float sinv[QBLK];
    const int qb = blockIdx.x, h = blockIdx.y, b = blockIdx.z;
    const int tid = threadIdx.x, wid = tid >> 5, lane = tid & 31;
    const int cntmax = (qb + 1) * QBLK;
    const size_t rs = 3 * EMB;
    const int l = qb * QBLK + wid;

    const float* qrow = qkv + ((size_t)(b * LSEQ + l)) * rs + h * DHEAD;
    float4 q[16];
#pragma unroll
    for (int i = 0; i < 16; ++i) q[i] = *(const float4*)(qrow + 4 * i);

    float lmax = -1e30f;
    for (int m = lane; m < cntmax; m += 32) {
        const float* kr = qkv + ((size_t)(b * LSEQ + m)) * rs + EMB + h * DHEAD;
        float dot = 0.f;
#pragma unroll
        for (int i = 0; i < 16; ++i) {
            float4 kv = *(const float4*)(kr + 4 * i);
            dot = fmaf(q[i].x, kv.x, dot); dot = fmaf(q[i].y, kv.y, dot);
            dot = fmaf(q[i].z, kv.z, dot); dot = fmaf(q[i].w, kv.w, dot);
        }
        dot *= 0.125f;
        sc[wid][m] = dot;
        if (m <= l) lmax = fmaxf(lmax, dot);
    }
#pragma unroll
    for (int o = 16; o; o >>= 1) lmax = fmaxf(lmax, __shfl_xor_sync(~0u, lmax, o));
    float lsum = 0.f;
    for (int m = lane; m < cntmax; m += 32) {
        float e = (m <= l) ? __expf(sc[wid][m] - lmax) : 0.f;
        sc[wid][m] = e; lsum += e;
    }
#pragma unroll
    for (int o = 16; o; o >>= 1) lsum += __shfl_xor_sync(~0u, lsum, o);
    if (lane == 0) sinv[wid] = 1.f / lsum;
    __syncthreads();

    const int seg = tid >> 6, d = tid & 63;
    float acc[QBLK];
#pragma unroll
    for (int j = 0; j < QBLK; ++j) acc[j] = 0.f;
    for (int m = seg; m < cntmax; m += 4) {
        const float vv = qkv[((size_t)(b * LSEQ + m)) * rs + 2 * EMB + h * DHEAD + d];
#pragma unroll
        for (int j = 0; j < QBLK; ++j) acc[j] = fmaf(sc[j][m], vv, acc[j]);
    }
#pragma unroll
    for (int j = 0; j < QBLK; ++j) red[seg][j][d] = acc[j];
    __syncthreads();
#pragma unroll
    for (int t = 0; t < 2; ++t) {
        const int j = (tid >> 6) + t * 4;
        const float o4 = (red[0][j][d] + red[1][j][d] + red[2][j][d] + red[3][j][d]) * sinv[j];
        const int lq = qb * QBLK + j;
        Oh[((size_t)(b * LSEQ + lq)) * EMB + h * DHEAD + d] = __float2half_rn(o4);
    }
}

// ---------------------------------------------------------------------------
// Head
// ---------------------------------------------------------------------------
__global__ void head_kernel(const float* __restrict__ x, const float* __restrict__ w_out,
                            const float* __restrict__ b_out, float* __restrict__ out)
{
    __shared__ float red[256];
    const int idx = blockIdx.x, b = idx / KLEN, k = idx % KLEN, tid = threadIdx.x;
    const float* xr = x + ((size_t)(b * LSEQ + 2 * k)) * EMB;
    float acc = 0.f;
#pragma unroll
    for (int c = tid; c < EMB; c += 256) acc = fmaf(xr[c], w_out[c], acc);
    red[tid] = acc;
    __syncthreads();
    for (int off = 128; off > 0; off >>= 1) {
        if (tid < off) red[tid] += red[tid + off];
        __syncthreads();
    }
    if (tid == 0) out[idx] = red[0] + b_out[0];
}

// ---------------------------------------------------------------------------
// Launch
// ---------------------------------------------------------------------------
extern "C" void kernel_launch(void* const* d_in, const int* in_sizes, int n_in,
                              void* d_out, int out_size)
{
    const float* xs     = (const float*)d_in[0];
    const float* ys     = (const float*)d_in[1];
    const float* w_in   = (const float*)d_in[2];
    const float* b_in   = (const float*)d_in[3];
    const float* qkv_w  = (const float*)d_in[4];
    const float* qkv_b  = (const float*)d_in[5];
    const float* proj_w = (const float*)d_in[6];
    const float* proj_b = (const float*)d_in[7];
    const float* ln1_s  = (const float*)d_in[8];
    const float* ln1_b  = (const float*)d_in[9];
    const float* ln2_s  = (const float*)d_in[10];
    const float* ln2_b  = (const float*)d_in[11];
    const float* mlp_w1 = (const float*)d_in[12];
    const float* mlp_b1 = (const float*)d_in[13];
    const float* mlp_w2 = (const float*)d_in[14];
    const float* mlp_b2 = (const float*)d_in[15];
    const float* w_out  = (const float*)d_in[16];
    const float* b_out  = (const float*)d_in[17];
    float* out = (float*)d_out;

    float *x, *qkv;
    __half *hbuf, *abuf, *fbuf;
    __half *wqh, *wql, *wph, *wpl, *w1h, *w1l, *w2h, *w2l;
    cudaGetSymbolAddress((void**)&x,    g_x);
    cudaGetSymbolAddress((void**)&qkv,  g_qkv);
    cudaGetSymbolAddress((void**)&hbuf, g_h);
    cudaGetSymbolAddress((void**)&abuf, g_a);
    cudaGetSymbolAddress((void**)&fbuf, g_f);
    cudaGetSymbolAddress((void**)&wqh, g_wqh); cudaGetSymbolAddress((void**)&wql, g_wql);
    cudaGetSymbolAddress((void**)&wph, g_wph); cudaGetSymbolAddress((void**)&wpl, g_wpl);
    cudaGetSymbolAddress((void**)&w1h, g_w1h); cudaGetSymbolAddress((void**)&w1l, g_w1l);
    cudaGetSymbolAddress((void**)&w2h, g_w2h); cudaGetSymbolAddress((void**)&w2l, g_w2l);

    cudaFuncSetAttribute(gemm_mma<false, false, true,  false>, cudaFuncAttributeMaxDynamicSharedMemorySize, GEMM_SMEM);
    cudaFuncSetAttribute(gemm_mma<true,  false, true,  false>, cudaFuncAttributeMaxDynamicSharedMemorySize, GEMM_SMEM);
    cudaFuncSetAttribute(gemm_mma<false, true,  false, true >, cudaFuncAttributeMaxDynamicSharedMemorySize, GEMM_SMEM);

    const int M = MROWS;

    // launch 0: all weight transposes in one kernel
    transpose_split_all<<<dim3(12288, NLAYER), dim3(32, 8)>>>(
        qkv_w, proj_w, mlp_w1, mlp_w2, wqh, wql, wph, wpl, w1h, w1l, w2h, w2l);
    // launch 1
    embed_kernel<<<dim3(EMB / 256, M), 256>>>(xs, ys, w_in, b_in);

    for (int lay = 0; lay < NLAYER; ++lay) {
        const float* qb  = qkv_b  + (size_t)lay * 3 * EMB;
        const float* pb  = proj_b + (size_t)lay * EMB;
        const float* s1  = ln1_s  + (size_t)lay * EMB;
        const float* c1  = ln1_b  + (size_t)lay * EMB;
        const float* s2  = ln2_s  + (size_t)lay * EMB;
        const float* c2  = ln2_b  + (size_t)lay * EMB;
        const float* bb1 = mlp_b1 + (size_t)lay * FFDIM;
        const float* bb2 = mlp_b2 + (size_t)lay * EMB;
        const __half* lwqh = wqh + (size_t)lay * 3 * EMB * EMB;
        const __half* lwql = wql + (size_t)lay * 3 * EMB * EMB;
        const __half* lwph = wph + (size_t)lay * EMB * EMB;
        const __half* lwpl = wpl + (size_t)lay * EMB * EMB;
        const __half* lw1h = w1h + (size_t)lay * FFDIM * EMB;
        const __half* lw1l = w1l + (size_t)lay * FFDIM * EMB;
        const __half* lw2h = w2h + (size_t)lay * EMB * FFDIM;
        const __half* lw2l = w2l + (size_t)lay * EMB * FFDIM;

        // launches 2..6 in layer 0: ln, gemm_qkv, attn, gemm_proj(idx5), ...
        ln_kernel<<<M, 256>>>(x, s1, c1, hbuf);
        gemm_mma<false, false, true, false><<<dim3(3 * EMB / 128, M / 128), 512, GEMM_SMEM>>>(
            hbuf, lwqh, lwql, qb, nullptr, qkv, nullptr, M, 3 * EMB, EMB);
        attn_kernel<<<dim3(LSEQ / QBLK, NHEAD, BATCH), 256>>>(qkv, abuf);
        gemm_mma<true, false, true, false><<<dim3(EMB / 128, M / 128), 512, GEMM_SMEM>>>(
            abuf, lwph, lwpl, pb, x, x, nullptr, M, EMB, EMB);
        ln_kernel<<<M, 256>>>(x, s2, c2, hbuf);
        gemm_mma<false, true, false, true><<<dim3(FFDIM / 128, M / 128), 512, GEMM_SMEM>>>(
            hbuf, lw1h, lw1l, bb1, nullptr, nullptr, fbuf, M, FFDIM, EMB);
        gemm_mma<true, false, true, false><<<dim3(EMB / 128, M / 128), 512, GEMM_SMEM>>>(
            fbuf, lw2h, lw2l, bb2, x, x, nullptr, M, EMB, FFDIM);
    }

    head_kernel<<<BATCH * KLEN, 256>>>(x, w_out, b_out, out);
}

// round 6
// speedup vs baseline: 9.9877x; 2.6027x over previous
#include <cuda_runtime.h>
#include <cuda_fp16.h>
#include <cuda_bf16.h>
#include <math.h>
#include <stdint.h>

#define BATCH 2
#define KLEN  512
#define LSEQ  1024
#define EMB   1024
#define NHEAD 16
#define DHEAD 64
#define NLAYER 12
#define FFDIM 4096
#define DIN   64
#define LN_EPS 1e-5f
#define MROWS (BATCH * LSEQ)   // 2048
#define NBH   (BATCH * NHEAD)  // 32

// ---------------------------------------------------------------------------
// Scratch (device globals; zero-initialized at load; allocation forbidden)
// ---------------------------------------------------------------------------
__device__ float g_x [MROWS * EMB];
__device__ __half g_h[MROWS * EMB];       // ln out (fp16)
__device__ __half g_a[MROWS * EMB];       // attn out (fp16)
__device__ __half g_f[MROWS * FFDIM];     // mlp hidden (fp16)
// attention operands (bf16 hi/lo)
__device__ __nv_bfloat16 g_qh[NBH * LSEQ * DHEAD];
__device__ __nv_bfloat16 g_ql[NBH * LSEQ * DHEAD];
__device__ __nv_bfloat16 g_kh[NBH * LSEQ * DHEAD];
__device__ __nv_bfloat16 g_kl[NBH * LSEQ * DHEAD];
__device__ __nv_bfloat16 g_vth[NBH * 128 * LSEQ];   // V transposed, rows 64..127 stay 0
__device__ __nv_bfloat16 g_vtl[NBH * 128 * LSEQ];
__device__ float         g_s [ (size_t)NBH * LSEQ * LSEQ ];   // scores fp32 (128 MB)
__device__ __nv_bfloat16 g_ph[ (size_t)NBH * LSEQ * LSEQ ];   // probs hi
__device__ __nv_bfloat16 g_pl[ (size_t)NBH * LSEQ * LSEQ ];   // probs lo
// transposed + split weights: [layer][N][K], fp16 hi + lo
__device__ __half g_wqh[NLAYER * 3 * EMB * EMB];
__device__ __half g_wql[NLAYER * 3 * EMB * EMB];
__device__ __half g_wph[NLAYER * EMB * EMB];
__device__ __half g_wpl[NLAYER * EMB * EMB];
__device__ __half g_w1h[NLAYER * FFDIM * EMB];
__device__ __half g_w1l[NLAYER * FFDIM * EMB];
__device__ __half g_w2h[NLAYER * EMB * FFDIM];
__device__ __half g_w2l[NLAYER * EMB * FFDIM];

// ---------------------------------------------------------------------------
// Helpers
// ---------------------------------------------------------------------------
__device__ __forceinline__ uint32_t smem_u32(const void* p) {
    uint32_t a;
    asm("{ .reg .u64 t; cvta.to.shared.u64 t, %1; cvt.u32.u64 %0, t; }" : "=r"(a) : "l"(p));
    return a;
}
__device__ __forceinline__ void cp_async16(uint32_t s, const void* g) {
    asm volatile("cp.async.cg.shared.global [%0], [%1], 16;" :: "r"(s), "l"(g));
}
#define CP_COMMIT() asm volatile("cp.async.commit_group;" ::: "memory")
#define CP_WAIT(n)  asm volatile("cp.async.wait_group %0;" :: "n"(n) : "memory")

__device__ __forceinline__ void ldsm4(uint32_t a, uint32_t& r0, uint32_t& r1,
                                      uint32_t& r2, uint32_t& r3) {
    asm volatile("ldmatrix.sync.aligned.m8n8.x4.shared.b16 {%0,%1,%2,%3}, [%4];"
                 : "=r"(r0), "=r"(r1), "=r"(r2), "=r"(r3) : "r"(a));
}
__device__ __forceinline__ void mma_f16(float* d, const uint32_t* a, const uint32_t* b) {
    asm volatile(
        "mma.sync.aligned.m16n8k16.row.col.f32.f16.f16.f32 "
        "{%0,%1,%2,%3}, {%4,%5,%6,%7}, {%8,%9}, {%0,%1,%2,%3};"
        : "+f"(d[0]), "+f"(d[1]), "+f"(d[2]), "+f"(d[3])
        : "r"(a[0]), "r"(a[1]), "r"(a[2]), "r"(a[3]), "r"(b[0]), "r"(b[1]));
}
__device__ __forceinline__ void mma_bf16(float* d, const uint32_t* a, const uint32_t* b) {
    asm volatile(
        "mma.sync.aligned.m16n8k16.row.col.f32.bf16.bf16.f32 "
        "{%0,%1,%2,%3}, {%4,%5,%6,%7}, {%8,%9}, {%0,%1,%2,%3};"
        : "+f"(d[0]), "+f"(d[1]), "+f"(d[2]), "+f"(d[3])
        : "r"(a[0]), "r"(a[1]), "r"(a[2]), "r"(a[3]), "r"(b[0]), "r"(b[1]));
}
__device__ __forceinline__ void split_f16(float v, __half& hi, __half& lo) {
    hi = __float2half_rn(v);
    lo = __float2half_rn(v - __half2float(hi));
}
__device__ __forceinline__ void split_bf(float v, __nv_bfloat16& hi, __nv_bfloat16& lo) {
    hi = __float2bfloat16(v);
    lo = __float2bfloat16(v - __bfloat162float(hi));
}

// ---------------------------------------------------------------------------
// Fused weight transpose + split (ONE launch)
// ---------------------------------------------------------------------------
__global__ void transpose_split_all(
    const float* __restrict__ qkv_w, const float* __restrict__ proj_w,
    const float* __restrict__ mlp_w1, const float* __restrict__ mlp_w2)
{
    __shared__ float t[32][33];
    const int lay = blockIdx.y;
    int tt = blockIdx.x;
    const float* W; __half *Th, *Tl; int K, N;
    if (tt < 3072)      { W = qkv_w;  Th = g_wqh; Tl = g_wql; K = EMB;   N = 3 * EMB; }
    else if (tt < 4096) { W = proj_w; Th = g_wph; Tl = g_wpl; K = EMB;   N = EMB;   tt -= 3072; }
    else if (tt < 8192) { W = mlp_w1; Th = g_w1h; Tl = g_w1l; K = EMB;   N = FFDIM; tt -= 4096; }
    else                { W = mlp_w2; Th = g_w2h; Tl = g_w2l; K = FFDIM; N = EMB;   tt -= 8192; }
    const int ntx = N >> 5;
    const int n0 = (tt % ntx) * 32, k0 = (tt / ntx) * 32;
    const float* Ws = W + (size_t)lay * K * N;
    __half* Ths = Th + (size_t)lay * K * N;
    __half* Tls = Tl + (size_t)lay * K * N;
    for (int i = threadIdx.y; i < 32; i += 8)
        t[i][threadIdx.x] = Ws[(size_t)(k0 + i) * N + n0 + threadIdx.x];
    __syncthreads();
    for (int i = threadIdx.y; i < 32; i += 8) {
        float v = t[threadIdx.x][i];
        __half hi, lo; split_f16(v, hi, lo);
        size_t o = (size_t)(n0 + i) * K + k0 + threadIdx.x;
        Ths[o] = hi; Tls[o] = lo;
    }
}

// ---------------------------------------------------------------------------
// Embed
// ---------------------------------------------------------------------------
__global__ void embed_kernel(const float* __restrict__ xs, const float* __restrict__ ys,
                             const float* __restrict__ w_in, const float* __restrict__ b_in)
{
    __shared__ float z[DIN];
    const int row = blockIdx.y, b = row / LSEQ, l = row % LSEQ, k = l >> 1;
    const int tid = threadIdx.x;
    if (tid < DIN) {
        float v;
        if ((l & 1) == 0) v = xs[(b * KLEN + k) * DIN + tid];
        else              v = (tid == 0) ? ys[b * KLEN + k] : 0.0f;
        z[tid] = v;
    }
    __syncthreads();
    const int n = blockIdx.x * blockDim.x + tid;
    float acc = b_in[n];
#pragma unroll 16
    for (int d = 0; d < DIN; ++d) acc += z[d] * w_in[d * EMB + n];
    g_x[row * EMB + n] = acc;
}

// ---------------------------------------------------------------------------
// LayerNorm -> fp16
// ---------------------------------------------------------------------------
__global__ void ln_kernel(const float* __restrict__ x,
                          const float* __restrict__ s, const float* __restrict__ bb,
                          __half* __restrict__ oh)
{
    __shared__ float r1[256], r2[256], stats[2];
    const int row = blockIdx.x, tid = threadIdx.x;
    const float* xr = x + (size_t)row * EMB;
    float sum = 0.f, sq = 0.f;
#pragma unroll
    for (int c = tid; c < EMB; c += 256) { float v = xr[c]; sum += v; sq += v * v; }
    r1[tid] = sum; r2[tid] = sq;
    __syncthreads();
    for (int off = 128; off > 0; off >>= 1) {
        if (tid < off) { r1[tid] += r1[tid + off]; r2[tid] += r2[tid + off]; }
        __syncthreads();
    }
    if (tid == 0) {
        float m = r1[0] * (1.0f / EMB);
        float v = r2[0] * (1.0f / EMB) - m * m;
        stats[0] = m; stats[1] = rsqrtf(v + LN_EPS);
    }
    __syncthreads();
    const float m = stats[0], rstd = stats[1];
#pragma unroll
    for (int c = tid; c < EMB; c += 256) {
        float v = (xr[c] - m) * rstd * s[c] + bb[c];
        oh[(size_t)row * EMB + c] = __float2half_rn(v);
    }
}

// ---------------------------------------------------------------------------
// 2-term fp16 GEMM (weights path). 128x128 tile, 512 thr, 4-stage cp.async.
// EPI: 0 = write qkv splits (Q,K head-major bf16 hi/lo; V transposed)
//      1 = residual + fp32 out   2 = GELU + fp16 out
// ---------------------------------------------------------------------------
#define RSTRIDE 80
#define MAT_BYTES (128 * RSTRIDE)
#define STAGE_BYTES (3 * MAT_BYTES)
#define NSTAGE 4
#define GEMM_SMEM (NSTAGE * STAGE_BYTES)   // 122880

template <int EPI>
__global__ void __launch_bounds__(512, 1) gemm_mma(
    const __half* __restrict__ A,
    const __half* __restrict__ Bh, const __half* __restrict__ Bl,
    const float* __restrict__ bias, const float* __restrict__ Rres,
    float* __restrict__ C, __half* __restrict__ Ch,
    int M, int N, int K)
{
    extern __shared__ char smem[];
    const uint32_t sbase = smem_u32(smem);
    const int tid = threadIdx.x, wid = tid >> 5, lane = tid & 31;
    const int m0 = blockIdx.y * 128, n0 = blockIdx.x * 128;
    const int wm = wid & 3, wn = wid >> 2;
    const int g = lane >> 2, q = lane & 3;
    const int lrow = tid >> 2, lch = tid & 3;
    const uint32_t soff = (uint32_t)(lrow * RSTRIDE + lch * 16);
    const uint32_t aoff = (uint32_t)((wm * 32 + (lane & 15)) * RSTRIDE + (lane >> 4) * 16);
    const uint32_t boff = (uint32_t)((wn * 32 + (lane >> 4) * 8 + (lane & 7)) * RSTRIDE
                                     + ((lane >> 3) & 1) * 16);

    float acc[2][4][4];
#pragma unroll
    for (int i = 0; i < 2; ++i)
#pragma unroll
        for (int j = 0; j < 4; ++j)
#pragma unroll
            for (int r = 0; r < 4; ++r) acc[i][j][r] = 0.f;

    const int CH = K >> 5;
    auto load_stage = [&](int c) {
        const int k0 = c << 5;
        const uint32_t sb = sbase + (c & (NSTAGE - 1)) * STAGE_BYTES + soff;
        const size_t ga = (size_t)(m0 + lrow) * K + k0 + lch * 8;
        const size_t gb = (size_t)(n0 + lrow) * K + k0 + lch * 8;
        cp_async16(sb,                 A  + ga);
        cp_async16(sb + MAT_BYTES,     Bh + gb);
        cp_async16(sb + 2 * MAT_BYTES, Bl + gb);
    };
    load_stage(0); CP_COMMIT();
    load_stage(1); CP_COMMIT();
    load_stage(2); CP_COMMIT();

    for (int c = 0; c < CH; ++c) {
        CP_WAIT(2);
        __syncthreads();
        const uint32_t sA = sbase + (c & (NSTAGE - 1)) * STAGE_BYTES;
        const uint32_t sB = sA + MAT_BYTES;
#pragma unroll
        for (int ks = 0; ks < 2; ++ks) {
            uint32_t Af[2][4], Bhf[4][2], Blf[4][2];
#pragma unroll
            for (int mt = 0; mt < 2; ++mt) {
                const uint32_t aa = sA + aoff + mt * 16 * RSTRIDE + ks * 32;
                ldsm4(aa, Af[mt][0], Af[mt][1], Af[mt][2], Af[mt][3]);
            }
#pragma unroll
            for (int p = 0; p < 2; ++p) {
                const uint32_t ba = sB + boff + p * 16 * RSTRIDE + ks * 32;
                ldsm4(ba,             Bhf[2*p][0], Bhf[2*p][1], Bhf[2*p+1][0], Bhf[2*p+1][1]);
                ldsm4(ba + MAT_BYTES, Blf[2*p][0], Blf[2*p][1], Blf[2*p+1][0], Blf[2*p+1][1]);
            }
#pragma unroll
            for (int mt = 0; mt < 2; ++mt)
#pragma unroll
                for (int nt = 0; nt < 4; ++nt)
                    mma_f16(acc[mt][nt], Af[mt], Bhf[nt]);
#pragma unroll
            for (int mt = 0; mt < 2; ++mt)
#pragma unroll
                for (int nt = 0; nt < 4; ++nt)
                    mma_f16(acc[mt][nt], Af[mt], Blf[nt]);
        }
        if (c + 3 < CH) load_stage(c + 3);
        CP_COMMIT();
    }

#pragma unroll
    for (int nt = 0; nt < 4; ++nt) {
        const int col = n0 + wn * 32 + nt * 8 + q * 2;
        const float bia0 = bias[col], bia1 = bias[col + 1];
#pragma unroll
        for (int mt = 0; mt < 2; ++mt) {
#pragma unroll
            for (int h2 = 0; h2 < 2; ++h2) {
                const int row = m0 + wm * 32 + mt * 16 + g + h2 * 8;
                float v0 = acc[mt][nt][h2 * 2 + 0] + bia0;
                float v1 = acc[mt][nt][h2 * 2 + 1] + bia1;
                if (EPI == 0) {
                    // write Q/K head-major bf16 hi/lo, V transposed
                    const int b = row >> 10, l = row & 1023;
                    const int part = col >> 10;
                    const int h = (col & 1023) >> 6, d = col & 63;
                    const int bh = b * NHEAD + h;
                    __nv_bfloat16 h0, l0, h1, l1;
                    split_bf(v0, h0, l0); split_bf(v1, h1, l1);
                    if (part == 2) {
                        const size_t o = ((size_t)bh * 128 + d) * LSEQ + l;
                        g_vth[o] = h0; g_vtl[o] = l0;
                        g_vth[o + LSEQ] = h1; g_vtl[o + LSEQ] = l1;
                    } else {
                        const size_t o = ((size_t)bh * LSEQ + l) * DHEAD + d;
                        __nv_bfloat162 hv; hv.x = h0; hv.y = h1;
                        __nv_bfloat162 lv; lv.x = l0; lv.y = l1;
                        if (part == 0) {
                            *(__nv_bfloat162*)(g_qh + o) = hv;
                            *(__nv_bfloat162*)(g_ql + o) = lv;
                        } else {
                            *(__nv_bfloat162*)(g_kh + o) = hv;
                            *(__nv_bfloat162*)(g_kl + o) = lv;
                        }
                    }
                } else {
                    const size_t o = (size_t)row * N + col;
                    if (EPI == 1) {
                        v0 += Rres[o]; v1 += Rres[o + 1];
                        float2 fv = {v0, v1}; *(float2*)(C + o) = fv;
                    } else {
                        v0 = 0.5f * v0 * (1.0f + erff(v0 * 0.70710678118654752f));
                        v1 = 0.5f * v1 * (1.0f + erff(v1 * 0.70710678118654752f));
                        __half2 hv; hv.x = __float2half_rn(v0); hv.y = __float2half_rn(v1);
                        *(__half2*)(Ch + o) = hv;
                    }
                }
            }
        }
    }
}

// ---------------------------------------------------------------------------
// 3-term bf16 batched GEMM for attention.
// MODE 0: S = Q·K^T  (per bh; M=N=1024, K=64; skip tiles above diagonal)
// MODE 1: O = P·Vt^T (per bh; M=1024, N=128 (64 used), K=Keff=m0+128)
// ---------------------------------------------------------------------------
#define RS3 80
#define MB3 (128 * RS3)
#define SB3 (4 * MB3)          // 40960
#define NS3 3
#define SMEM3 (NS3 * SB3)      // 122880

template <int MODE>
__global__ void __launch_bounds__(512, 1) gemm3_bf16()
{
    extern __shared__ char smem[];
    const uint32_t sbase = smem_u32(smem);
    const int tid = threadIdx.x, wid = tid >> 5, lane = tid & 31;
    const int bh = blockIdx.z;
    const int m0 = blockIdx.y * 128, n0 = blockIdx.x * 128;
    if (MODE == 0 && n0 > m0 + 127) return;

    const int Kdim = (MODE == 0) ? DHEAD : LSEQ;
    const int CH = (MODE == 0) ? 2 : ((m0 + 128) >> 5);

    const __nv_bfloat16 *Ah, *Al, *Bh, *Bl;
    if (MODE == 0) {
        const size_t ab = (size_t)bh * LSEQ * DHEAD;
        Ah = g_qh + ab; Al = g_ql + ab; Bh = g_kh + ab; Bl = g_kl + ab;
    } else {
        const size_t ab = (size_t)bh * LSEQ * LSEQ;
        const size_t bb = (size_t)bh * 128 * LSEQ;
        Ah = g_ph + ab; Al = g_pl + ab; Bh = g_vth + bb; Bl = g_vtl + bb;
    }

    const int wm = wid & 3, wn = wid >> 2;
    const int g = lane >> 2, q = lane & 3;
    const int lrow = tid >> 2, lch = tid & 3;
    const uint32_t soff = (uint32_t)(lrow * RS3 + lch * 16);
    const uint32_t aoff = (uint32_t)((wm * 32 + (lane & 15)) * RS3 + (lane >> 4) * 16);
    const uint32_t boff = (uint32_t)((wn * 32 + (lane >> 4) * 8 + (lane & 7)) * RS3
                                     + ((lane >> 3) & 1) * 16);

    float acc[2][4][4];
#pragma unroll
    for (int i = 0; i < 2; ++i)
#pragma unroll
        for (int j = 0; j < 4; ++j)
#pragma unroll
            for (int r = 0; r < 4; ++r) acc[i][j][r] = 0.f;

    auto load_stage = [&](int c) {
        const int k0 = c << 5;
        const uint32_t sb = sbase + (c % NS3) * SB3 + soff;
        const size_t ga = (size_t)(m0 + lrow) * Kdim + k0 + lch * 8;
        const size_t gb = (size_t)(n0 + lrow) * Kdim + k0 + lch * 8;
        cp_async16(sb,           Ah + ga);
        cp_async16(sb + MB3,     Al + ga);
        cp_async16(sb + 2 * MB3, Bh + gb);
        cp_async16(sb + 3 * MB3, Bl + gb);
    };
    load_stage(0); CP_COMMIT();
    if (CH > 1) load_stage(1);
    CP_COMMIT();

    for (int c = 0; c < CH; ++c) {
        CP_WAIT(1);
        __syncthreads();
        const uint32_t sA = sbase + (c % NS3) * SB3;
        const uint32_t sB = sA + 2 * MB3;
#pragma unroll
        for (int ks = 0; ks < 2; ++ks) {
            uint32_t Ahf[2][4], Alf[2][4], Bhf[4][2], Blf[4][2];
#pragma unroll
            for (int mt = 0; mt < 2; ++mt) {
                const uint32_t aa = sA + aoff + mt * 16 * RS3 + ks * 32;
                ldsm4(aa,       Ahf[mt][0], Ahf[mt][1], Ahf[mt][2], Ahf[mt][3]);
                ldsm4(aa + MB3, Alf[mt][0], Alf[mt][1], Alf[mt][2], Alf[mt][3]);
            }
#pragma unroll
            for (int p = 0; p < 2; ++p) {
                const uint32_t ba = sB + boff + p * 16 * RS3 + ks * 32;
                ldsm4(ba,       Bhf[2*p][0], Bhf[2*p][1], Bhf[2*p+1][0], Bhf[2*p+1][1]);
                ldsm4(ba + MB3, Blf[2*p][0], Blf[2*p][1], Blf[2*p+1][0], Blf[2*p+1][1]);
            }
#pragma unroll
            for (int mt = 0; mt < 2; ++mt)
#pragma unroll
                for (int nt = 0; nt < 4; ++nt)
                    mma_bf16(acc[mt][nt], Ahf[mt], Bhf[nt]);
#pragma unroll
            for (int mt = 0; mt < 2; ++mt)
#pragma unroll
                for (int nt = 0; nt < 4; ++nt)
                    mma_bf16(acc[mt][nt], Ahf[mt], Blf[nt]);
#pragma unroll
            for (int mt = 0; mt < 2; ++mt)
#pragma unroll
                for (int nt = 0; nt < 4; ++nt)
                    mma_bf16(acc[mt][nt], Alf[mt], Bhf[nt]);
        }
        if (c + 2 < CH) load_stage(c + 2);
        CP_COMMIT();
    }

    if (MODE == 0) {
        float* Sp = g_s + ((size_t)bh << 20);
#pragma unroll
        for (int nt = 0; nt < 4; ++nt) {
            const int col = n0 + wn * 32 + nt * 8 + q * 2;
#pragma unroll
            for (int mt = 0; mt < 2; ++mt)
#pragma unroll
                for (int h2 = 0; h2 < 2; ++h2) {
                    const int row = m0 + wm * 32 + mt * 16 + g + h2 * 8;
                    float2 fv = {acc[mt][nt][h2 * 2], acc[mt][nt][h2 * 2 + 1]};
                    *(float2*)(Sp + ((size_t)row << 10) + col) = fv;
                }
        }
    } else {
        const int b = bh >> 4, hh = bh & 15;
#pragma unroll
        for (int nt = 0; nt < 4; ++nt) {
            const int col = wn * 32 + nt * 8 + q * 2;
            if (col < DHEAD) {
#pragma unroll
                for (int mt = 0; mt < 2; ++mt)
#pragma unroll
                    for (int h2 = 0; h2 < 2; ++h2) {
                        const int row = m0 + wm * 32 + mt * 16 + g + h2 * 8;
                        __half2 hv;
                        hv.x = __float2half_rn(acc[mt][nt][h2 * 2]);
                        hv.y = __float2half_rn(acc[mt][nt][h2 * 2 + 1]);
                        *(__half2*)(g_a + ((size_t)(b * LSEQ + row)) * EMB
                                    + hh * DHEAD + col) = hv;
                    }
            }
        }
    }
}

// ---------------------------------------------------------------------------
// Softmax: one row per block; scale 1/8, causal, write P bf16 hi/lo (zeros past l)
// ---------------------------------------------------------------------------
__global__ void __launch_bounds__(256) softmax_kernel()
{
    __shared__ float e[LSEQ];
    __shared__ float red[256];
    const int rowid = blockIdx.x;
    const int bh = rowid >> 10, l = rowid & 1023;
    const float* sr = g_s + ((size_t)bh << 20) + ((size_t)l << 10);
    const int tid = threadIdx.x;

    float mx = -1e30f;
    for (int k = tid; k <= l; k += 256) mx = fmaxf(mx, sr[k]);
    red[tid] = mx;
    __syncthreads();
    for (int o = 128; o; o >>= 1) {
        if (tid < o) red[tid] = fmaxf(red[tid], red[tid + o]);
        __syncthreads();
    }
    const float mraw = red[0];
    __syncthreads();

    float sum = 0.f;
    for (int k = tid; k < LSEQ; k += 256) {
        float v = (k <= l) ? __expf((sr[k] - mraw) * 0.125f) : 0.f;
        e[k] = v; sum += v;
    }
    red[tid] = sum;
    __syncthreads();
    for (int o = 128; o; o >>= 1) {
        if (tid < o) red[tid] += red[tid + o];
        __syncthreads();
    }
    const float inv = 1.0f / red[0];

    const size_t base = ((size_t)bh << 20) + ((size_t)l << 10);
    for (int k = tid * 2; k < LSEQ; k += 512) {
        float p0 = e[k] * inv, p1 = e[k + 1] * inv;
        __nv_bfloat16 h0, l0, h1, l1;
        split_bf(p0, h0, l0); split_bf(p1, h1, l1);
        __nv_bfloat162 hv; hv.x = h0; hv.y = h1;
        __nv_bfloat162 lv; lv.x = l0; lv.y = l1;
        *(__nv_bfloat162*)(g_ph + base + k) = hv;
        *(__nv_bfloat162*)(g_pl + base + k) = lv;
    }
}

// ---------------------------------------------------------------------------
// Head
// ---------------------------------------------------------------------------
__global__ void head_kernel(const float* __restrict__ x, const float* __restrict__ w_out,
                            const float* __restrict__ b_out, float* __restrict__ out)
{
    __shared__ float red[256];
    const int idx = blockIdx.x, b = idx / KLEN, k = idx % KLEN, tid = threadIdx.x;
    const float* xr = x + ((size_t)(b * LSEQ + 2 * k)) * EMB;
    float acc = 0.f;
#pragma unroll
    for (int c = tid; c < EMB; c += 256) acc = fmaf(xr[c], w_out[c], acc);
    red[tid] = acc;
    __syncthreads();
    for (int off = 128; off > 0; off >>= 1) {
        if (tid < off) red[tid] += red[tid + off];
        __syncthreads();
    }
    if (tid == 0) out[idx] = red[0] + b_out[0];
}

// ---------------------------------------------------------------------------
// Launch
// ---------------------------------------------------------------------------
extern "C" void kernel_launch(void* const* d_in, const int* in_sizes, int n_in,
                              void* d_out, int out_size)
{
    const float* xs     = (const float*)d_in[0];
    const float* ys     = (const float*)d_in[1];
    const float* w_in   = (const float*)d_in[2];
    const float* b_in   = (const float*)d_in[3];
    const float* qkv_w  = (const float*)d_in[4];
    const float* qkv_b  = (const float*)d_in[5];
    const float* proj_w = (const float*)d_in[6];
    const float* proj_b = (const float*)d_in[7];
    const float* ln1_s  = (const float*)d_in[8];
    const float* ln1_b  = (const float*)d_in[9];
    const float* ln2_s  = (const float*)d_in[10];
    const float* ln2_b  = (const float*)d_in[11];
    const float* mlp_w1 = (const float*)d_in[12];
    const float* mlp_b1 = (const float*)d_in[13];
    const float* mlp_w2 = (const float*)d_in[14];
    const float* mlp_b2 = (const float*)d_in[15];
    const float* w_out  = (const float*)d_in[16];
    const float* b_out  = (const float*)d_in[17];
    float* out = (float*)d_out;

    float* x;
    __half *hbuf, *abuf, *fbuf;
    __half *wqh, *wql, *wph, *wpl, *w1h, *w1l, *w2h, *w2l;
    cudaGetSymbolAddress((void**)&x,    g_x);
    cudaGetSymbolAddress((void**)&hbuf, g_h);
    cudaGetSymbolAddress((void**)&abuf, g_a);
    cudaGetSymbolAddress((void**)&fbuf, g_f);
    cudaGetSymbolAddress((void**)&wqh, g_wqh); cudaGetSymbolAddress((void**)&wql, g_wql);
    cudaGetSymbolAddress((void**)&wph, g_wph); cudaGetSymbolAddress((void**)&wpl, g_wpl);
    cudaGetSymbolAddress((void**)&w1h, g_w1h); cudaGetSymbolAddress((void**)&w1l, g_w1l);
    cudaGetSymbolAddress((void**)&w2h, g_w2h); cudaGetSymbolAddress((void**)&w2l, g_w2l);

    cudaFuncSetAttribute(gemm_mma<0>, cudaFuncAttributeMaxDynamicSharedMemorySize, GEMM_SMEM);
    cudaFuncSetAttribute(gemm_mma<1>, cudaFuncAttributeMaxDynamicSharedMemorySize, GEMM_SMEM);
    cudaFuncSetAttribute(gemm_mma<2>, cudaFuncAttributeMaxDynamicSharedMemorySize, GEMM_SMEM);
    cudaFuncSetAttribute(gemm3_bf16<0>, cudaFuncAttributeMaxDynamicSharedMemorySize, SMEM3);
    cudaFuncSetAttribute(gemm3_bf16<1>, cudaFuncAttributeMaxDynamicSharedMemorySize, SMEM3);

    const int M = MROWS;

    transpose_split_all<<<dim3(12288, NLAYER), dim3(32, 8)>>>(qkv_w, proj_w, mlp_w1, mlp_w2);
    embed_kernel<<<dim3(EMB / 256, M), 256>>>(xs, ys, w_in, b_in);

    for (int lay = 0; lay < NLAYER; ++lay) {
        const float* qb  = qkv_b  + (size_t)lay * 3 * EMB;
        const float* pb  = proj_b + (size_t)lay * EMB;
        const float* s1  = ln1_s  + (size_t)lay * EMB;
        const float* c1  = ln1_b  + (size_t)lay * EMB;
        const float* s2  = ln2_s  + (size_t)lay * EMB;
        const float* c2  = ln2_b  + (size_t)lay * EMB;
        const float* bb1 = mlp_b1 + (size_t)lay * FFDIM;
        const float* bb2 = mlp_b2 + (size_t)lay * EMB;
        const __half* lwqh = wqh + (size_t)lay * 3 * EMB * EMB;
        const __half* lwql = wql + (size_t)lay * 3 * EMB * EMB;
        const __half* lwph = wph + (size_t)lay * EMB * EMB;
        const __half* lwpl = wpl + (size_t)lay * EMB * EMB;
        const __half* lw1h = w1h + (size_t)lay * FFDIM * EMB;
        const __half* lw1l = w1l + (size_t)lay * FFDIM * EMB;
        const __half* lw2h = w2h + (size_t)lay * EMB * FFDIM;
        const __half* lw2l = w2l + (size_t)lay * EMB * FFDIM;

        ln_kernel<<<M, 256>>>(x, s1, c1, hbuf);
        gemm_mma<0><<<dim3(3 * EMB / 128, M / 128), 512, GEMM_SMEM>>>(
            hbuf, lwqh, lwql, qb, nullptr, nullptr, nullptr, M, 3 * EMB, EMB);
        gemm3_bf16<0><<<dim3(8, 8, NBH), 512, SMEM3>>>();
        softmax_kernel<<<NBH * LSEQ, 256>>>();
        gemm3_bf16<1><<<dim3(1, 8, NBH), 512, SMEM3>>>();
        gemm_mma<1><<<dim3(EMB / 128, M / 128), 512, GEMM_SMEM>>>(
            abuf, lwph, lwpl, pb, x, x, nullptr, M, EMB, EMB);
        ln_kernel<<<M, 256>>>(x, s2, c2, hbuf);
        gemm_mma<2><<<dim3(FFDIM / 128, M / 128), 512, GEMM_SMEM>>>(
            hbuf, lw1h, lw1l, bb1, nullptr, nullptr, fbuf, M, FFDIM, EMB);
        gemm_mma<1><<<dim3(EMB / 128, M / 128), 512, GEMM_SMEM>>>(
            fbuf, lw2h, lw2l, bb2, x, x, nullptr, M, EMB, FFDIM);
    }

    head_kernel<<<BATCH * KLEN, 256>>>(x, w_out, b_out, out);
}

// round 7
// speedup vs baseline: 13.7633x; 1.3780x over previous
#include <cuda_runtime.h>
#include <cuda_fp16.h>
#include <cuda_bf16.h>
#include <math.h>
#include <stdint.h>

#define BATCH 2
#define KLEN  512
#define LSEQ  1024
#define EMB   1024
#define NHEAD 16
#define DHEAD 64
#define NLAYER 12
#define FFDIM 4096
#define DIN   64
#define LN_EPS 1e-5f
#define MROWS (BATCH * LSEQ)   // 2048
#define NBH   (BATCH * NHEAD)  // 32

// ---------------------------------------------------------------------------
// Scratch (device globals; zero-initialized; allocation forbidden)
// ---------------------------------------------------------------------------
__device__ float g_x [MROWS * EMB];
__device__ __half g_h[MROWS * EMB];       // ln out (fp16)
__device__ __half g_a[MROWS * EMB];       // attn out (fp16)
__device__ __half g_f[MROWS * FFDIM];     // mlp hidden (fp16)
// attention operands (bf16 hi/lo)
__device__ __nv_bfloat16 g_qh[NBH * LSEQ * DHEAD];
__device__ __nv_bfloat16 g_ql[NBH * LSEQ * DHEAD];
__device__ __nv_bfloat16 g_kh[NBH * LSEQ * DHEAD];
__device__ __nv_bfloat16 g_kl[NBH * LSEQ * DHEAD];
__device__ __nv_bfloat16 g_vth[NBH * DHEAD * LSEQ];   // V transposed [bh][d][l]
__device__ __nv_bfloat16 g_vtl[NBH * DHEAD * LSEQ];
// transposed + split weights: [layer][N][K], fp16 hi + lo
__device__ __half g_wqh[NLAYER * 3 * EMB * EMB];
__device__ __half g_wql[NLAYER * 3 * EMB * EMB];
__device__ __half g_wph[NLAYER * EMB * EMB];
__device__ __half g_wpl[NLAYER * EMB * EMB];
__device__ __half g_w1h[NLAYER * FFDIM * EMB];
__device__ __half g_w1l[NLAYER * FFDIM * EMB];
__device__ __half g_w2h[NLAYER * EMB * FFDIM];
__device__ __half g_w2l[NLAYER * EMB * FFDIM];

// ---------------------------------------------------------------------------
// Helpers
// ---------------------------------------------------------------------------
__device__ __forceinline__ uint32_t smem_u32(const void* p) {
    uint32_t a;
    asm("{ .reg .u64 t; cvta.to.shared.u64 t, %1; cvt.u32.u64 %0, t; }" : "=r"(a) : "l"(p));
    return a;
}
__device__ __forceinline__ void cp_async16(uint32_t s, const void* g) {
    asm volatile("cp.async.cg.shared.global [%0], [%1], 16;" :: "r"(s), "l"(g));
}
#define CP_COMMIT() asm volatile("cp.async.commit_group;" ::: "memory")
#define CP_WAIT(n)  asm volatile("cp.async.wait_group %0;" :: "n"(n) : "memory")

__device__ __forceinline__ void ldsm4(uint32_t a, uint32_t& r0, uint32_t& r1,
                                      uint32_t& r2, uint32_t& r3) {
    asm volatile("ldmatrix.sync.aligned.m8n8.x4.shared.b16 {%0,%1,%2,%3}, [%4];"
                 : "=r"(r0), "=r"(r1), "=r"(r2), "=r"(r3) : "r"(a));
}
__device__ __forceinline__ void mma_f16(float* d, const uint32_t* a, const uint32_t* b) {
    asm volatile(
        "mma.sync.aligned.m16n8k16.row.col.f32.f16.f16.f32 "
        "{%0,%1,%2,%3}, {%4,%5,%6,%7}, {%8,%9}, {%0,%1,%2,%3};"
        : "+f"(d[0]), "+f"(d[1]), "+f"(d[2]), "+f"(d[3])
        : "r"(a[0]), "r"(a[1]), "r"(a[2]), "r"(a[3]), "r"(b[0]), "r"(b[1]));
}
__device__ __forceinline__ void mma_bf16(float* d, const uint32_t* a, const uint32_t* b) {
    asm volatile(
        "mma.sync.aligned.m16n8k16.row.col.f32.bf16.bf16.f32 "
        "{%0,%1,%2,%3}, {%4,%5,%6,%7}, {%8,%9}, {%0,%1,%2,%3};"
        : "+f"(d[0]), "+f"(d[1]), "+f"(d[2]), "+f"(d[3])
        : "r"(a[0]), "r"(a[1]), "r"(a[2]), "r"(a[3]), "r"(b[0]), "r"(b[1]));
}
__device__ __forceinline__ void split_f16(float v, __half& hi, __half& lo) {
    hi = __float2half_rn(v);
    lo = __float2half_rn(v - __half2float(hi));
}
__device__ __forceinline__ void split_bf(float v, __nv_bfloat16& hi, __nv_bfloat16& lo) {
    hi = __float2bfloat16(v);
    lo = __float2bfloat16(v - __bfloat162float(hi));
}
// pack two fp32 -> bf16x2 (hi reg value = v1, lo = v0), plus residual pack
__device__ __forceinline__ void split_pack(float v0, float v1, uint32_t& ph, uint32_t& pl) {
    asm("cvt.rn.bf16x2.f32 %0, %1, %2;" : "=r"(ph) : "f"(v1), "f"(v0));
    float h0 = __uint_as_float(ph << 16);
    float h1 = __uint_as_float(ph & 0xFFFF0000u);
    float r0 = v0 - h0, r1 = v1 - h1;
    asm("cvt.rn.bf16x2.f32 %0, %1, %2;" : "=r"(pl) : "f"(r1), "f"(r0));
}

// ---------------------------------------------------------------------------
// Fused weight transpose + split (ONE launch)
// ---------------------------------------------------------------------------
__global__ void transpose_split_all(
    const float* __restrict__ qkv_w, const float* __restrict__ proj_w,
    const float* __restrict__ mlp_w1, const float* __restrict__ mlp_w2)
{
    __shared__ float t[32][33];
    const int lay = blockIdx.y;
    int tt = blockIdx.x;
    const float* W; __half *Th, *Tl; int K, N;
    if (tt < 3072)      { W = qkv_w;  Th = g_wqh; Tl = g_wql; K = EMB;   N = 3 * EMB; }
    else if (tt < 4096) { W = proj_w; Th = g_wph; Tl = g_wpl; K = EMB;   N = EMB;   tt -= 3072; }
    else if (tt < 8192) { W = mlp_w1; Th = g_w1h; Tl = g_w1l; K = EMB;   N = FFDIM; tt -= 4096; }
    else                { W = mlp_w2; Th = g_w2h; Tl = g_w2l; K = FFDIM; N = EMB;   tt -= 8192; }
    const int ntx = N >> 5;
    const int n0 = (tt % ntx) * 32, k0 = (tt / ntx) * 32;
    const float* Ws = W + (size_t)lay * K * N;
    __half* Ths = Th + (size_t)lay * K * N;
    __half* Tls = Tl + (size_t)lay * K * N;
    for (int i = threadIdx.y; i < 32; i += 8)
        t[i][threadIdx.x] = Ws[(size_t)(k0 + i) * N + n0 + threadIdx.x];
    __syncthreads();
    for (int i = threadIdx.y; i < 32; i += 8) {
        float v = t[threadIdx.x][i];
        __half hi, lo; split_f16(v, hi, lo);
        size_t o = (size_t)(n0 + i) * K + k0 + threadIdx.x;
        Ths[o] = hi; Tls[o] = lo;
    }
}

// ---------------------------------------------------------------------------
// Embed
// ---------------------------------------------------------------------------
__global__ void embed_kernel(const float* __restrict__ xs, const float* __restrict__ ys,
                             const float* __restrict__ w_in, const float* __restrict__ b_in)
{
    __shared__ float z[DIN];
    const int row = blockIdx.y, b = row / LSEQ, l = row % LSEQ, k = l >> 1;
    const int tid = threadIdx.x;
    if (tid < DIN) {
        float v;
        if ((l & 1) == 0) v = xs[(b * KLEN + k) * DIN + tid];
        else              v = (tid == 0) ? ys[b * KLEN + k] : 0.0f;
        z[tid] = v;
    }
    __syncthreads();
    const int n = blockIdx.x * blockDim.x + tid;
    float acc = b_in[n];
#pragma unroll 16
    for (int d = 0; d < DIN; ++d) acc += z[d] * w_in[d * EMB + n];
    g_x[row * EMB + n] = acc;
}

// ---------------------------------------------------------------------------
// LayerNorm -> fp16
// ---------------------------------------------------------------------------
__global__ void ln_kernel(const float* __restrict__ x,
                          const float* __restrict__ s, const float* __restrict__ bb,
                          __half* __restrict__ oh)
{
    __shared__ float r1[256], r2[256], stats[2];
    const int row = blockIdx.x, tid = threadIdx.x;
    const float* xr = x + (size_t)row * EMB;
    float sum = 0.f, sq = 0.f;
#pragma unroll
    for (int c = tid; c < EMB; c += 256) { float v = xr[c]; sum += v; sq += v * v; }
    r1[tid] = sum; r2[tid] = sq;
    __syncthreads();
    for (int off = 128; off > 0; off >>= 1) {
        if (tid < off) { r1[tid] += r1[tid + off]; r2[tid] += r2[tid + off]; }
        __syncthreads();
    }
    if (tid == 0) {
        float m = r1[0] * (1.0f / EMB);
        float v = r2[0] * (1.0f / EMB) - m * m;
        stats[0] = m; stats[1] = rsqrtf(v + LN_EPS);
    }
    __syncthreads();
    const float m = stats[0], rstd = stats[1];
#pragma unroll
    for (int c = tid; c < EMB; c += 256) {
        float v = (xr[c] - m) * rstd * s[c] + bb[c];
        oh[(size_t)row * EMB + c] = __float2half_rn(v);
    }
}

// ---------------------------------------------------------------------------
// 2-term fp16 GEMM (weights path). 128x128 tile, 512 thr, 4-stage cp.async.
// EPI: 0 = write qkv splits   1 = residual + fp32 out   2 = GELU + fp16 out
// ---------------------------------------------------------------------------
#define RSTRIDE 80
#define MAT_BYTES (128 * RSTRIDE)
#define STAGE_BYTES (3 * MAT_BYTES)
#define NSTAGE 4
#define GEMM_SMEM (NSTAGE * STAGE_BYTES)   // 122880

template <int EPI>
__global__ void __launch_bounds__(512, 1) gemm_mma(
    const __half* __restrict__ A,
    const __half* __restrict__ Bh, const __half* __restrict__ Bl,
    const float* __restrict__ bias, const float* __restrict__ Rres,
    float* __restrict__ C, __half* __restrict__ Ch,
    int M, int N, int K)
{
    extern __shared__ char smem[];
    const uint32_t sbase = smem_u32(smem);
    const int tid = threadIdx.x, wid = tid >> 5, lane = tid & 31;
    const int m0 = blockIdx.y * 128, n0 = blockIdx.x * 128;
    const int wm = wid & 3, wn = wid >> 2;
    const int g = lane >> 2, q = lane & 3;
    const int lrow = tid >> 2, lch = tid & 3;
    const uint32_t soff = (uint32_t)(lrow * RSTRIDE + lch * 16);
    const uint32_t aoff = (uint32_t)((wm * 32 + (lane & 15)) * RSTRIDE + (lane >> 4) * 16);
    const uint32_t boff = (uint32_t)((wn * 32 + (lane >> 4) * 8 + (lane & 7)) * RSTRIDE
                                     + ((lane >> 3) & 1) * 16);

    float acc[2][4][4];
#pragma unroll
    for (int i = 0; i < 2; ++i)
#pragma unroll
        for (int j = 0; j < 4; ++j)
#pragma unroll
            for (int r = 0; r < 4; ++r) acc[i][j][r] = 0.f;

    const int CH = K >> 5;
    auto load_stage = [&](int c) {
        const int k0 = c << 5;
        const uint32_t sb = sbase + (c & (NSTAGE - 1)) * STAGE_BYTES + soff;
        const size_t ga = (size_t)(m0 + lrow) * K + k0 + lch * 8;
        const size_t gb = (size_t)(n0 + lrow) * K + k0 + lch * 8;
        cp_async16(sb,                 A  + ga);
        cp_async16(sb + MAT_BYTES,     Bh + gb);
        cp_async16(sb + 2 * MAT_BYTES, Bl + gb);
    };
    load_stage(0); CP_COMMIT();
    load_stage(1); CP_COMMIT();
    load_stage(2); CP_COMMIT();

    for (int c = 0; c < CH; ++c) {
        CP_WAIT(2);
        __syncthreads();
        const uint32_t sA = sbase + (c & (NSTAGE - 1)) * STAGE_BYTES;
        const uint32_t sB = sA + MAT_BYTES;
#pragma unroll
        for (int ks = 0; ks < 2; ++ks) {
            uint32_t Af[2][4], Bhf[4][2], Blf[4][2];
#pragma unroll
            for (int mt = 0; mt < 2; ++mt) {
                const uint32_t aa = sA + aoff + mt * 16 * RSTRIDE + ks * 32;
                ldsm4(aa, Af[mt][0], Af[mt][1], Af[mt][2], Af[mt][3]);
            }
#pragma unroll
            for (int p = 0; p < 2; ++p) {
                const uint32_t ba = sB + boff + p * 16 * RSTRIDE + ks * 32;
                ldsm4(ba,             Bhf[2*p][0], Bhf[2*p][1], Bhf[2*p+1][0], Bhf[2*p+1][1]);
                ldsm4(ba + MAT_BYTES, Blf[2*p][0], Blf[2*p][1], Blf[2*p+1][0], Blf[2*p+1][1]);
            }
#pragma unroll
            for (int mt = 0; mt < 2; ++mt)
#pragma unroll
                for (int nt = 0; nt < 4; ++nt)
                    mma_f16(acc[mt][nt], Af[mt], Bhf[nt]);
#pragma unroll
            for (int mt = 0; mt < 2; ++mt)
#pragma unroll
                for (int nt = 0; nt < 4; ++nt)
                    mma_f16(acc[mt][nt], Af[mt], Blf[nt]);
        }
        if (c + 3 < CH) load_stage(c + 3);
        CP_COMMIT();
    }

#pragma unroll
    for (int nt = 0; nt < 4; ++nt) {
        const int col = n0 + wn * 32 + nt * 8 + q * 2;
        const float bia0 = bias[col], bia1 = bias[col + 1];
#pragma unroll
        for (int mt = 0; mt < 2; ++mt) {
#pragma unroll
            for (int h2 = 0; h2 < 2; ++h2) {
                const int row = m0 + wm * 32 + mt * 16 + g + h2 * 8;
                float v0 = acc[mt][nt][h2 * 2 + 0] + bia0;
                float v1 = acc[mt][nt][h2 * 2 + 1] + bia1;
                if (EPI == 0) {
                    const int b = row >> 10, l = row & 1023;
                    const int part = col >> 10;
                    const int h = (col & 1023) >> 6, d = col & 63;
                    const int bh = b * NHEAD + h;
                    __nv_bfloat16 h0, l0, h1, l1;
                    split_bf(v0, h0, l0); split_bf(v1, h1, l1);
                    if (part == 2) {
                        const size_t o = ((size_t)bh * DHEAD + d) * LSEQ + l;
                        g_vth[o] = h0; g_vtl[o] = l0;
                        g_vth[o + LSEQ] = h1; g_vtl[o + LSEQ] = l1;
                    } else {
                        const size_t o = ((size_t)bh * LSEQ + l) * DHEAD + d;
                        __nv_bfloat162 hv; hv.x = h0; hv.y = h1;
                        __nv_bfloat162 lv; lv.x = l0; lv.y = l1;
                        if (part == 0) {
                            *(__nv_bfloat162*)(g_qh + o) = hv;
                            *(__nv_bfloat162*)(g_ql + o) = lv;
                        } else {
                            *(__nv_bfloat162*)(g_kh + o) = hv;
                            *(__nv_bfloat162*)(g_kl + o) = lv;
                        }
                    }
                } else {
                    const size_t o = (size_t)row * N + col;
                    if (EPI == 1) {
                        v0 += Rres[o]; v1 += Rres[o + 1];
                        float2 fv = {v0, v1}; *(float2*)(C + o) = fv;
                    } else {
                        v0 = 0.5f * v0 * (1.0f + erff(v0 * 0.70710678118654752f));
                        v1 = 0.5f * v1 * (1.0f + erff(v1 * 0.70710678118654752f));
                        __half2 hv; hv.x = __float2half_rn(v0); hv.y = __float2half_rn(v1);
                        *(__half2*)(Ch + o) = hv;
                    }
                }
            }
        }
    }
}

// ---------------------------------------------------------------------------
// Flash attention: one CTA per (bh, 128-query block). 256 threads = 8 warps,
// warp w owns rows w*16..w*16+15. S (3-term bf16) -> online softmax in regs
// -> O += P·V (3-term). K/V^T double-buffered via cp.async.
// ---------------------------------------------------------------------------
#define QRS 144
#define KRS 144
#define VRS 272
#define QB (128 * QRS)             // 18432
#define KBY (128 * KRS)            // 18432
#define VBY (64 * VRS)             // 17408
#define KVSTAGE (2 * KBY + 2 * VBY)  // 71680
#define FLASH_SMEM (2 * QB + 2 * KVSTAGE)  // 180224

__global__ void __launch_bounds__(256, 1) flash_attn()
{
    extern __shared__ char smem[];
    const uint32_t sb = smem_u32(smem);
    const int tid = threadIdx.x, wid = tid >> 5, lane = tid & 31;
    const int g = lane >> 2, q = lane & 3;
    const int bh = blockIdx.x;
    const int m0 = (7 - (int)blockIdx.y) * 128;     // heavy blocks first
    const int nkt = (m0 >> 7) + 1;

    const __nv_bfloat16* Qh = g_qh + (size_t)bh * LSEQ * DHEAD;
    const __nv_bfloat16* Ql = g_ql + (size_t)bh * LSEQ * DHEAD;
    const __nv_bfloat16* Kh = g_kh + (size_t)bh * LSEQ * DHEAD;
    const __nv_bfloat16* Kl = g_kl + (size_t)bh * LSEQ * DHEAD;
    const __nv_bfloat16* Vh = g_vth + (size_t)bh * DHEAD * LSEQ;
    const __nv_bfloat16* Vl = g_vtl + (size_t)bh * DHEAD * LSEQ;

    // Q tile -> smem
    for (int i = tid; i < 1024; i += 256) {
        const int row = i >> 3, ch = i & 7;
        const uint32_t so = sb + row * QRS + ch * 16;
        cp_async16(so,      Qh + (size_t)(m0 + row) * DHEAD + ch * 8);
        cp_async16(so + QB, Ql + (size_t)(m0 + row) * DHEAD + ch * 8);
    }
    auto load_kv = [&](int kt) {
        const int k0 = kt << 7;
        const uint32_t st = sb + 2 * QB + (kt & 1) * KVSTAGE;
        for (int i = tid; i < 1024; i += 256) {
            const int row = i >> 3, ch = i & 7;
            const uint32_t so = st + row * KRS + ch * 16;
            cp_async16(so,       Kh + (size_t)(k0 + row) * DHEAD + ch * 8);
            cp_async16(so + KBY, Kl + (size_t)(k0 + row) * DHEAD + ch * 8);
        }
        for (int i = tid; i < 1024; i += 256) {
            const int row = i >> 4, ch = i & 15;
            const uint32_t so = st + 2 * KBY + row * VRS + ch * 16;
            cp_async16(so,       Vh + (size_t)row * LSEQ + k0 + ch * 8);
            cp_async16(so + VBY, Vl + (size_t)row * LSEQ + k0 + ch * 8);
        }
    };
    load_kv(0);
    CP_COMMIT();   // group: Q + kv0

    const uint32_t aoff = (uint32_t)((wid * 16 + (lane & 15)) * QRS + (lane >> 4) * 16);
    const uint32_t bKoff = (uint32_t)(((lane >> 4) * 8 + (lane & 7)) * KRS + ((lane >> 3) & 1) * 16);
    const uint32_t bVoff = (uint32_t)(((lane >> 4) * 8 + (lane & 7)) * VRS + ((lane >> 3) & 1) * 16);

    float mrow[2] = {-1e30f, -1e30f};
    float lrow[2] = {0.f, 0.f};
    float Oa[8][4];
#pragma unroll
    for (int i = 0; i < 8; ++i)
#pragma unroll
        for (int j = 0; j < 4; ++j) Oa[i][j] = 0.f;

    for (int kt = 0; kt < nkt; ++kt) {
        if (kt + 1 < nkt) load_kv(kt + 1);
        CP_COMMIT();
        CP_WAIT(1);
        __syncthreads();

        const uint32_t st = sb + 2 * QB + (kt & 1) * KVSTAGE;
        float sacc[16][4];
#pragma unroll
        for (int i = 0; i < 16; ++i)
#pragma unroll
            for (int j = 0; j < 4; ++j) sacc[i][j] = 0.f;

        // ---- S = Q K^T (3-term bf16 split) ----
#pragma unroll
        for (int ks = 0; ks < 4; ++ks) {
            uint32_t Qf[4], Qg[4];
            ldsm4(sb + aoff + ks * 32,      Qf[0], Qf[1], Qf[2], Qf[3]);
            ldsm4(sb + QB + aoff + ks * 32, Qg[0], Qg[1], Qg[2], Qg[3]);
#pragma unroll
            for (int p = 0; p < 8; ++p) {
                uint32_t bh2[2][2], bl2[2][2];
                ldsm4(st + bKoff + p * 16 * KRS + ks * 32,
                      bh2[0][0], bh2[0][1], bh2[1][0], bh2[1][1]);
                ldsm4(st + KBY + bKoff + p * 16 * KRS + ks * 32,
                      bl2[0][0], bl2[0][1], bl2[1][0], bl2[1][1]);
                mma_bf16(sacc[2*p],   Qf, bh2[0]);
                mma_bf16(sacc[2*p+1], Qf, bh2[1]);
                mma_bf16(sacc[2*p],   Qf, bl2[0]);
                mma_bf16(sacc[2*p+1], Qf, bl2[1]);
                mma_bf16(sacc[2*p],   Qg, bh2[0]);
                mma_bf16(sacc[2*p+1], Qg, bh2[1]);
            }
        }

        // ---- causal mask on diagonal tile ----
        if (kt == nkt - 1) {
            const int rl0 = wid * 16 + g;
#pragma unroll
            for (int nt = 0; nt < 16; ++nt) {
                const int c0 = nt * 8 + q * 2;
                if (c0 > rl0)         sacc[nt][0] = -1e30f;
                if (c0 + 1 > rl0)     sacc[nt][1] = -1e30f;
                if (c0 > rl0 + 8)     sacc[nt][2] = -1e30f;
                if (c0 + 1 > rl0 + 8) sacc[nt][3] = -1e30f;
            }
        }

        // ---- online softmax (scaled domain; quad shfl reductions) ----
#pragma unroll
        for (int r = 0; r < 2; ++r) {
            float mx = -1e30f;
#pragma unroll
            for (int nt = 0; nt < 16; ++nt)
                mx = fmaxf(mx, fmaxf(sacc[nt][2*r], sacc[nt][2*r+1]));
            mx = fmaxf(mx, __shfl_xor_sync(~0u, mx, 1));
            mx = fmaxf(mx, __shfl_xor_sync(~0u, mx, 2));
            mx *= 0.125f;
            const float mnew = fmaxf(mrow[r], mx);
            const float alpha = __expf(mrow[r] - mnew);
            mrow[r] = mnew;
            float ls = 0.f;
#pragma unroll
            for (int nt = 0; nt < 16; ++nt) {
                float p0 = __expf(fmaf(sacc[nt][2*r], 0.125f, -mnew));
                float p1 = __expf(fmaf(sacc[nt][2*r+1], 0.125f, -mnew));
                sacc[nt][2*r] = p0; sacc[nt][2*r+1] = p1;
                ls += p0 + p1;
            }
            lrow[r] = lrow[r] * alpha + ls;
#pragma unroll
            for (int nt = 0; nt < 8; ++nt) {
                Oa[nt][2*r] *= alpha; Oa[nt][2*r+1] *= alpha;
            }
        }

        // ---- O += P V (P hi/lo packed from S accumulators in-register) ----
#pragma unroll
        for (int ks = 0; ks < 8; ++ks) {
            uint32_t Ph[4], Pl[4];
            split_pack(sacc[2*ks][0],   sacc[2*ks][1],   Ph[0], Pl[0]);
            split_pack(sacc[2*ks][2],   sacc[2*ks][3],   Ph[1], Pl[1]);
            split_pack(sacc[2*ks+1][0], sacc[2*ks+1][1], Ph[2], Pl[2]);
            split_pack(sacc[2*ks+1][2], sacc[2*ks+1][3], Ph[3], Pl[3]);
#pragma unroll
            for (int p = 0; p < 4; ++p) {
                uint32_t vh2[2][2], vl2[2][2];
                ldsm4(st + 2 * KBY + bVoff + p * 16 * VRS + ks * 32,
                      vh2[0][0], vh2[0][1], vh2[1][0], vh2[1][1]);
                ldsm4(st + 2 * KBY + VBY + bVoff + p * 16 * VRS + ks * 32,
                      vl2[0][0], vl2[0][1], vl2[1][0], vl2[1][1]);
                mma_bf16(Oa[2*p],   Ph, vh2[0]);
                mma_bf16(Oa[2*p+1], Ph, vh2[1]);
                mma_bf16(Oa[2*p],   Ph, vl2[0]);
                mma_bf16(Oa[2*p+1], Ph, vl2[1]);
                mma_bf16(Oa[2*p],   Pl, vh2[0]);
                mma_bf16(Oa[2*p+1], Pl, vh2[1]);
            }
        }
        __syncthreads();
    }

    // ---- epilogue: normalize, write fp16 token-major ----
    const int b = bh >> 4, hh = bh & 15;
#pragma unroll
    for (int r = 0; r < 2; ++r) {
        float l = lrow[r];
        l += __shfl_xor_sync(~0u, l, 1);
        l += __shfl_xor_sync(~0u, l, 2);
        const float inv = 1.0f / l;
        const int row = m0 + wid * 16 + g + r * 8;
#pragma unroll
        for (int nt = 0; nt < 8; ++nt) {
            __half2 hv;
            hv.x = __float2half_rn(Oa[nt][2*r] * inv);
            hv.y = __float2half_rn(Oa[nt][2*r+1] * inv);
            *(__half2*)(g_a + ((size_t)(b * LSEQ + row)) * EMB
                        + hh * DHEAD + nt * 8 + q * 2) = hv;
        }
    }
}

// ---------------------------------------------------------------------------
// Head
// ---------------------------------------------------------------------------
__global__ void head_kernel(const float* __restrict__ x, const float* __restrict__ w_out,
                            const float* __restrict__ b_out, float* __restrict__ out)
{
    __shared__ float red[256];
    const int idx = blockIdx.x, b = idx / KLEN, k = idx % KLEN, tid = threadIdx.x;
    const float* xr = x + ((size_t)(b * LSEQ + 2 * k)) * EMB;
    float acc = 0.f;
#pragma unroll
    for (int c = tid; c < EMB; c += 256) acc = fmaf(xr[c], w_out[c], acc);
    red[tid] = acc;
    __syncthreads();
    for (int off = 128; off > 0; off >>= 1) {
        if (tid < off) red[tid] += red[tid + off];
        __syncthreads();
    }
    if (tid == 0) out[idx] = red[0] + b_out[0];
}

// ---------------------------------------------------------------------------
// Launch
// ---------------------------------------------------------------------------
extern "C" void kernel_launch(void* const* d_in, const int* in_sizes, int n_in,
                              void* d_out, int out_size)
{
    const float* xs     = (const float*)d_in[0];
    const float* ys     = (const float*)d_in[1];
    const float* w_in   = (const float*)d_in[2];
    const float* b_in   = (const float*)d_in[3];
    const float* qkv_w  = (const float*)d_in[4];
    const float* qkv_b  = (const float*)d_in[5];
    const float* proj_w = (const float*)d_in[6];
    const float* proj_b = (const float*)d_in[7];
    const float* ln1_s  = (const float*)d_in[8];
    const float* ln1_b  = (const float*)d_in[9];
    const float* ln2_s  = (const float*)d_in[10];
    const float* ln2_b  = (const float*)d_in[11];
    const float* mlp_w1 = (const float*)d_in[12];
    const float* mlp_b1 = (const float*)d_in[13];
    const float* mlp_w2 = (const float*)d_in[14];
    const float* mlp_b2 = (const float*)d_in[15];
    const float* w_out  = (const float*)d_in[16];
    const float* b_out  = (const float*)d_in[17];
    float* out = (float*)d_out;

    float* x;
    __half *hbuf, *abuf, *fbuf;
    __half *wqh, *wql, *wph, *wpl, *w1h, *w1l, *w2h, *w2l;
    cudaGetSymbolAddress((void**)&x,    g_x);
    cudaGetSymbolAddress((void**)&hbuf, g_h);
    cudaGetSymbolAddress((void**)&abuf, g_a);
    cudaGetSymbolAddress((void**)&fbuf, g_f);
    cudaGetSymbolAddress((void**)&wqh, g_wqh); cudaGetSymbolAddress((void**)&wql, g_wql);
    cudaGetSymbolAddress((void**)&wph, g_wph); cudaGetSymbolAddress((void**)&wpl, g_wpl);
    cudaGetSymbolAddress((void**)&w1h, g_w1h); cudaGetSymbolAddress((void**)&w1l, g_w1l);
    cudaGetSymbolAddress((void**)&w2h, g_w2h); cudaGetSymbolAddress((void**)&w2l, g_w2l);

    cudaFuncSetAttribute(gemm_mma<0>, cudaFuncAttributeMaxDynamicSharedMemorySize, GEMM_SMEM);
    cudaFuncSetAttribute(gemm_mma<1>, cudaFuncAttributeMaxDynamicSharedMemorySize, GEMM_SMEM);
    cudaFuncSetAttribute(gemm_mma<2>, cudaFuncAttributeMaxDynamicSharedMemorySize, GEMM_SMEM);
    cudaFuncSetAttribute(flash_attn,  cudaFuncAttributeMaxDynamicSharedMemorySize, FLASH_SMEM);

    const int M = MROWS;

    transpose_split_all<<<dim3(12288, NLAYER), dim3(32, 8)>>>(qkv_w, proj_w, mlp_w1, mlp_w2);
    embed_kernel<<<dim3(EMB / 256, M), 256>>>(xs, ys, w_in, b_in);

    for (int lay = 0; lay < NLAYER; ++lay) {
        const float* qb  = qkv_b  + (size_t)lay * 3 * EMB;
        const float* pb  = proj_b + (size_t)lay * EMB;
        const float* s1  = ln1_s  + (size_t)lay * EMB;
        const float* c1  = ln1_b  + (size_t)lay * EMB;
        const float* s2  = ln2_s  + (size_t)lay * EMB;
        const float* c2  = ln2_b  + (size_t)lay * EMB;
        const float* bb1 = mlp_b1 + (size_t)lay * FFDIM;
        const float* bb2 = mlp_b2 + (size_t)lay * EMB;
        const __half* lwqh = wqh + (size_t)lay * 3 * EMB * EMB;
        const __half* lwql = wql + (size_t)lay * 3 * EMB * EMB;
        const __half* lwph = wph + (size_t)lay * EMB * EMB;
        const __half* lwpl = wpl + (size_t)lay * EMB * EMB;
        const __half* lw1h = w1h + (size_t)lay * FFDIM * EMB;
        const __half* lw1l = w1l + (size_t)lay * FFDIM * EMB;
        const __half* lw2h = w2h + (size_t)lay * EMB * FFDIM;
        const __half* lw2l = w2l + (size_t)lay * EMB * FFDIM;

        ln_kernel<<<M, 256>>>(x, s1, c1, hbuf);
        gemm_mma<0><<<dim3(3 * EMB / 128, M / 128), 512, GEMM_SMEM>>>(
            hbuf, lwqh, lwql, qb, nullptr, nullptr, nullptr, M, 3 * EMB, EMB);
        flash_attn<<<dim3(NBH, 8), 256, FLASH_SMEM>>>();
        gemm_mma<1><<<dim3(EMB / 128, M / 128), 512, GEMM_SMEM>>>(
            abuf, lwph, lwpl, pb, x, x, nullptr, M, EMB, EMB);
        ln_kernel<<<M, 256>>>(x, s2, c2, hbuf);
        gemm_mma<2><<<dim3(FFDIM / 128, M / 128), 512, GEMM_SMEM>>>(
            hbuf, lw1h, lw1l, bb1, nullptr, nullptr, fbuf, M, FFDIM, EMB);
        gemm_mma<1><<<dim3(EMB / 128, M / 128), 512, GEMM_SMEM>>>(
            fbuf, lw2h, lw2l, bb2, x, x, nullptr, M, EMB, FFDIM);
    }

    head_kernel<<<BATCH * KLEN, 256>>>(x, w_out, b_out, out);
}